// round 10
// baseline (speedup 1.0000x reference)
#include <cuda_runtime.h>
#include <mma.h>
#include <cstdint>

using namespace nvcuda;

#define Nn 2048
#define Dd 128
#define Cc 512
#define Kp 1024
#define TINV 14.285714285714286f

// ----------------- scratch (device globals; allocation-free) -----------------
__device__ float    g_fes[Nn*Dd], g_fet[Nn*Dd];
__device__ unsigned g_Abits[Nn*64];
__device__ float    g_dinv[Nn];
__device__ float    g_Mf[Nn*Nn];              // 16 MB dense masked-normalized adjacency
__device__ float    g_h1t[Nn*Dd], g_h1s[Nn*Dd], g_h2t[Nn*Dd], g_h2s[Nn*Dd];
__device__ float    g_fgt[Nn*Dd], g_fgs[Nn*Dd];
__device__ float    g_pp[2*8*Nn*Dd];          // 16 MB partial-prop scratch
__device__ float    g_rowp1[32*Nn], g_colp1[32*Nn];
__device__ float    g_pos1[Nn];
__device__ float    g_scores[Nn];
__device__ int      g_selidx[Kp];
__device__ float    g_selval[Kp];
__device__ float    g_nht[Kp*Dd], g_nhs[Kp*Dd];
__device__ unsigned g_Pbits[Kp*32];
__device__ float    g_dinvp[Kp];
__device__ float    g_Pf[Kp*Kp];              // 4 MB pooled adjacency
__device__ float    g_ph1t[Kp*Dd], g_ph1s[Kp*Dd];
__device__ float    g_fpt[Kp*Dd], g_fps[Kp*Dd];
__device__ float    g_rowp2[16*Kp], g_colp2[16*Kp];
__device__ float    g_pos2[Kp];

// ----------------- kernels -----------------

// OUT[16 rows] = l2norm(X @ W_embed + b). grid (Nn/16, 2): y=0 fs->fes, y=1 ft->fet. 128 thr.
__global__ void embed_kernel(const float* __restrict__ fs, const float* __restrict__ ft,
                             const float* __restrict__ W, const float* __restrict__ b) {
    const float* X = blockIdx.y ? ft : fs;
    float* OUT = blockIdx.y ? g_fet : g_fes;
    int d = threadIdx.x;
    int R0 = blockIdx.x * 16;
    __shared__ __align__(16) float srow[16][64];
    __shared__ float sW[64][Dd];
    __shared__ float sred[16][132];
    __shared__ float sscale[16];
    float acc[16];
#pragma unroll
    for (int r = 0; r < 16; r++) acc[r] = 0.f;
    for (int kc = 0; kc < Cc; kc += 64) {
        __syncthreads();
        for (int u = d; u < 256; u += Dd) { int r = u >> 4, kq = u & 15;
            ((float4*)srow[r])[kq] = *(const float4*)&X[(size_t)(R0 + r) * Cc + kc + kq*4]; }
        for (int k = 0; k < 64; k++) sW[k][d] = W[(size_t)(kc + k) * Dd + d];
        __syncthreads();
#pragma unroll 4
        for (int k4 = 0; k4 < 16; k4++) {
            float w0 = sW[k4*4+0][d], w1 = sW[k4*4+1][d], w2 = sW[k4*4+2][d], w3 = sW[k4*4+3][d];
#pragma unroll
            for (int r = 0; r < 16; r++) {
                float4 s4 = ((float4*)srow[r])[k4];
                acc[r] += s4.x*w0; acc[r] += s4.y*w1; acc[r] += s4.z*w2; acc[r] += s4.w*w3;
            }
        }
    }
    float bb = b[d];
#pragma unroll
    for (int r = 0; r < 16; r++) sred[r][d] = acc[r] + bb;
    __syncthreads();
    int lane = d & 31, w = d >> 5;
#pragma unroll
    for (int m = 0; m < 4; m++) {
        int r = w*4 + m;
        float x0 = sred[r][lane], x1 = sred[r][lane+32], x2 = sred[r][lane+64], x3 = sred[r][lane+96];
        float s = x0*x0 + x1*x1 + x2*x2 + x3*x3;
#pragma unroll
        for (int o = 16; o; o >>= 1) s += __shfl_xor_sync(0xffffffffu, s, o);
        if (lane == 0) sscale[r] = rsqrtf(s);
    }
    __syncthreads();
#pragma unroll
    for (int r = 0; r < 16; r++) OUT[(size_t)(R0 + r) * Dd + d] = sred[r][d] * sscale[r];
}

// TAGConv linear + l2norm (+ optional scores on teacher branch). grid (n/16, 2), 128 thr.
__global__ void lin_kernel(const float* __restrict__ X0t, const float* __restrict__ X1t,
                           const float* __restrict__ X2t,
                           const float* __restrict__ X0s, const float* __restrict__ X1s,
                           const float* __restrict__ X2s,
                           int nparts, const float* __restrict__ W, const float* __restrict__ b,
                           float* __restrict__ OUTt, float* __restrict__ OUTs,
                           const float* __restrict__ Wp, const float* __restrict__ bp,
                           int do_score) {
    const float* Xs[3];
    float* OUT;
    if (blockIdx.y) { Xs[0] = X0s; Xs[1] = X1s; Xs[2] = X2s; OUT = OUTs; }
    else            { Xs[0] = X0t; Xs[1] = X1t; Xs[2] = X2t; OUT = OUTt; }
    int d = threadIdx.x;
    int R0 = blockIdx.x * 16;
    __shared__ __align__(16) float srow[16][64];
    __shared__ float sW[64][Dd];
    __shared__ float sred[16][132];
    __shared__ float sscale[16];
    float acc[16];
#pragma unroll
    for (int r = 0; r < 16; r++) acc[r] = 0.f;
    int K = nparts * Dd;
    for (int kc = 0; kc < K; kc += 64) {
        const float* Xp = Xs[kc >> 7];
        int off = kc & 127;
        __syncthreads();
        for (int u = d; u < 256; u += Dd) { int r = u >> 4, kq = u & 15;
            ((float4*)srow[r])[kq] = *(const float4*)&Xp[(size_t)(R0 + r) * Dd + off + kq*4]; }
        for (int k = 0; k < 64; k++) sW[k][d] = W[(size_t)(kc + k) * Dd + d];
        __syncthreads();
#pragma unroll 4
        for (int k4 = 0; k4 < 16; k4++) {
            float w0 = sW[k4*4+0][d], w1 = sW[k4*4+1][d], w2 = sW[k4*4+2][d], w3 = sW[k4*4+3][d];
#pragma unroll
            for (int r = 0; r < 16; r++) {
                float4 s4 = ((float4*)srow[r])[k4];
                acc[r] += s4.x*w0; acc[r] += s4.y*w1; acc[r] += s4.z*w2; acc[r] += s4.w*w3;
            }
        }
    }
    float bb = b[d];
#pragma unroll
    for (int r = 0; r < 16; r++) sred[r][d] = acc[r] + bb;
    __syncthreads();
    int lane = d & 31, w = d >> 5;
    bool sc = do_score && (blockIdx.y == 0);
    float wp0 = 0.f, wp1 = 0.f, wp2 = 0.f, wp3 = 0.f;
    if (sc) { wp0 = Wp[lane]; wp1 = Wp[lane+32]; wp2 = Wp[lane+64]; wp3 = Wp[lane+96]; }
#pragma unroll
    for (int m = 0; m < 4; m++) {
        int r = w*4 + m;
        float x0 = sred[r][lane], x1 = sred[r][lane+32], x2 = sred[r][lane+64], x3 = sred[r][lane+96];
        float s = x0*x0 + x1*x1 + x2*x2 + x3*x3;
        float sp = x0*wp0 + x1*wp1 + x2*wp2 + x3*wp3;
#pragma unroll
        for (int o = 16; o; o >>= 1) { s += __shfl_xor_sync(0xffffffffu, s, o);
                                       sp += __shfl_xor_sync(0xffffffffu, sp, o); }
        if (lane == 0) {
            float scale = rsqrtf(s);
            sscale[r] = scale;
            if (sc) g_scores[R0 + r] = 1.f / (1.f + expf(-(sp * scale + bp[0])));
        }
    }
    __syncthreads();
#pragma unroll
    for (int r = 0; r < 16; r++) OUT[(size_t)(R0 + r) * Dd + d] = sred[r][d] * sscale[r];
}

// A = (fet @ fet^T > 0) with forced diag -> bitmask. Symmetric: lower-triangle tiles, mirrored.
__global__ void gramA_kernel() {
    int l = blockIdx.x;
    int by = (int)((sqrtf(8.f * l + 1.f) - 1.f) * 0.5f);
    while ((by + 1) * (by + 2) / 2 <= l) by++;
    while (by * (by + 1) / 2 > l) by--;
    int bx = l - by * (by + 1) / 2;
    int I0 = by * 64, J0 = bx * 64;
    __shared__ __align__(16) float sx[64*68];
    __shared__ __align__(16) float sy[64*68];
    __shared__ unsigned sbits[64][2], tbits[64][2];
    int t = threadIdx.x, tx = t & 15, ty = t >> 4;
    float acc[4][4];
#pragma unroll
    for (int a = 0; a < 4; a++)
#pragma unroll
        for (int c = 0; c < 4; c++) acc[a][c] = 0.f;
    for (int kc = 0; kc < Dd; kc += 64) {
        __syncthreads();
        for (int u = t; u < 4096; u += 256) { int k = u & 63, r = u >> 6;
            sx[k*68 + r] = g_fet[(size_t)(I0 + r) * Dd + kc + k];
            sy[k*68 + r] = g_fet[(size_t)(J0 + r) * Dd + kc + k]; }
        __syncthreads();
#pragma unroll 8
        for (int k = 0; k < 64; k++) {
            float4 a4 = *(const float4*)&sx[k*68 + ty*4];
            float4 b4 = *(const float4*)&sy[k*68 + tx*4];
            acc[0][0] += a4.x*b4.x; acc[0][1] += a4.x*b4.y; acc[0][2] += a4.x*b4.z; acc[0][3] += a4.x*b4.w;
            acc[1][0] += a4.y*b4.x; acc[1][1] += a4.y*b4.y; acc[1][2] += a4.y*b4.z; acc[1][3] += a4.y*b4.w;
            acc[2][0] += a4.z*b4.x; acc[2][1] += a4.z*b4.y; acc[2][2] += a4.z*b4.z; acc[2][3] += a4.z*b4.w;
            acc[3][0] += a4.w*b4.x; acc[3][1] += a4.w*b4.y; acc[3][2] += a4.w*b4.z; acc[3][3] += a4.w*b4.w;
        }
    }
    __syncthreads();
    if (t < 128) { ((unsigned*)sbits)[t] = 0; ((unsigned*)tbits)[t] = 0; }
    __syncthreads();
    int wj = (tx * 4) >> 5, shj = (tx * 4) & 31;
    int wi = (ty * 4) >> 5, shi = (ty * 4) & 31;
#pragma unroll
    for (int rr = 0; rr < 4; rr++) {
        int i = I0 + ty*4 + rr;
        unsigned nib = 0;
#pragma unroll
        for (int cc = 0; cc < 4; cc++) {
            int j = J0 + tx*4 + cc;
            if (acc[rr][cc] > 0.f || i == j) nib |= 1u << cc;
        }
        if (nib) atomicOr(&sbits[ty*4 + rr][wj], nib << shj);
    }
#pragma unroll
    for (int cc = 0; cc < 4; cc++) {
        int j = J0 + tx*4 + cc;
        unsigned nib = 0;
#pragma unroll
        for (int rr = 0; rr < 4; rr++) {
            int i = I0 + ty*4 + rr;
            if (acc[rr][cc] > 0.f || i == j) nib |= 1u << rr;
        }
        if (nib) atomicOr(&tbits[tx*4 + cc][wi], nib << shi);
    }
    __syncthreads();
    if (t < 128) {
        int il = t >> 1, ww = t & 1;
        g_Abits[(size_t)(I0 + il) * 64 + (J0 >> 5) + ww] = sbits[il][ww];
        g_Abits[(size_t)(J0 + il) * 64 + (I0 >> 5) + ww] = tbits[il][ww];
    }
}

__global__ void dinv_kernel() {
    int i = blockIdx.x * blockDim.x + threadIdx.x;
    if (i >= Nn) return;
    const uint4* p = (const uint4*)&g_Abits[(size_t)i * 64];
    int dg = 0;
#pragma unroll
    for (int w = 0; w < 16; w++) { uint4 v = p[w];
        dg += __popc(v.x) + __popc(v.y) + __popc(v.z) + __popc(v.w); }
    g_dinv[i] = rsqrtf((float)dg);
}

// Mf[i,j] = bit(i,j) ? dinv_i*dinv_j : 0. One thread per 32-bit word.
__global__ void build_mf(const unsigned* __restrict__ bits, const float* __restrict__ dinv,
                         float* __restrict__ Mf, int n, int nwords) {
    int w = blockIdx.x * blockDim.x + threadIdx.x;
    if (w >= n * nwords) return;
    int i = w / nwords, wc = w - i * nwords;
    unsigned word = bits[w];
    float di = dinv[i];
    int j0 = wc * 32;
    float4* o = (float4*)&Mf[(size_t)i * n + j0];
#pragma unroll
    for (int q = 0; q < 8; q++) {
        float4 r;
        r.x = (word >> (q*4+0)) & 1 ? di * dinv[j0 + q*4+0] : 0.f;
        r.y = (word >> (q*4+1)) & 1 ? di * dinv[j0 + q*4+1] : 0.f;
        r.z = (word >> (q*4+2)) & 1 ? di * dinv[j0 + q*4+2] : 0.f;
        r.w = (word >> (q*4+3)) & 1 ? di * dinv[j0 + q*4+3] : 0.f;
        o[q] = r;
    }
}

// partial = Mf[i-tile, jchunk] @ H[jchunk, :]  via tf32 wmma (fp32 accumulate).
// grid (n/64, 1, 2*ns); 256 thr = 8 warps: warp&3 -> i sub-tile(16), warp>>2 -> d half(64).
__global__ void __launch_bounds__(256) prop_mma(
        const float* __restrict__ Mf,
        const float* __restrict__ Ht, const float* __restrict__ Hs,
        float* __restrict__ pp, int n, int ns) {
    int z = blockIdx.z;
    int ts = z / ns, split = z - ts * ns;
    const float* H = ts ? Hs : Ht;
    int warp = threadIdx.x >> 5;
    int i0 = blockIdx.x * 64 + (warp & 3) * 16;
    int d0 = (warp >> 2) * 64;
    int chunk = n / ns, jb = split * chunk;
    wmma::fragment<wmma::accumulator, 16, 16, 8, float> c[4];
#pragma unroll
    for (int t = 0; t < 4; t++) wmma::fill_fragment(c[t], 0.f);
    wmma::fragment<wmma::matrix_a, 16, 16, 8, wmma::precision::tf32, wmma::row_major> a;
    wmma::fragment<wmma::matrix_b, 16, 16, 8, wmma::precision::tf32, wmma::row_major> b;
    for (int j = jb; j < jb + chunk; j += 8) {
        wmma::load_matrix_sync(a, Mf + (size_t)i0 * n + j, n);
#pragma unroll
        for (int t = 0; t < a.num_elements; t++) a.x[t] = wmma::__float_to_tf32(a.x[t]);
#pragma unroll
        for (int nt = 0; nt < 4; nt++) {
            wmma::load_matrix_sync(b, H + (size_t)j * Dd + d0 + nt * 16, Dd);
#pragma unroll
            for (int t = 0; t < b.num_elements; t++) b.x[t] = wmma::__float_to_tf32(b.x[t]);
            wmma::mma_sync(c[nt], a, b, c[nt]);
        }
    }
    float* out = pp + (size_t)(ts * ns + split) * n * Dd;
#pragma unroll
    for (int nt = 0; nt < 4; nt++)
        wmma::store_matrix_sync(out + (size_t)i0 * Dd + d0 + nt * 16, c[nt], Dd, wmma::mem_row_major);
}

// O = sum_k partial_k (dinv factors already folded into Mf). grid (n*32/256, 2), 256 thr.
__global__ void prop_combine2(float* __restrict__ Ot, float* __restrict__ Os, int n, int ns) {
    int ts = blockIdx.y;
    float* O = ts ? Os : Ot;
    int idx = blockIdx.x * blockDim.x + threadIdx.x;   // float4 index
    if (idx >= n * 32) return;
    float4 s = make_float4(0.f, 0.f, 0.f, 0.f);
    for (int k = 0; k < ns; k++) {
        float4 v = *(const float4*)&g_pp[(size_t)(ts * ns + k) * n * Dd + (size_t)idx * 4];
        s.x += v.x; s.y += v.y; s.z += v.z; s.w += v.w;
    }
    *(float4*)&O[(size_t)idx * 4] = s;
}

// G = X @ Y^T; per-tile partial row/col sums of exp((G-1)/T); diag tiles emit pos.
__global__ void gramnce_kernel(const float* __restrict__ X, const float* __restrict__ Y,
                               float* __restrict__ rowp, float* __restrict__ colp,
                               float* __restrict__ pos, int n) {
    __shared__ __align__(16) float sx[64*68];
    __shared__ __align__(16) float sy[64*68];
    __shared__ float cbuf[16][64];
    int t = threadIdx.x, tx = t & 15, ty = t >> 4;
    int I0 = blockIdx.y * 64, J0 = blockIdx.x * 64;
    float acc[4][4];
#pragma unroll
    for (int a = 0; a < 4; a++)
#pragma unroll
        for (int c = 0; c < 4; c++) acc[a][c] = 0.f;
    for (int kc = 0; kc < Dd; kc += 64) {
        __syncthreads();
        for (int u = t; u < 4096; u += 256) { int k = u & 63, r = u >> 6;
            sx[k*68 + r] = X[(size_t)(I0 + r) * Dd + kc + k];
            sy[k*68 + r] = Y[(size_t)(J0 + r) * Dd + kc + k]; }
        __syncthreads();
#pragma unroll 8
        for (int k = 0; k < 64; k++) {
            float4 a4 = *(const float4*)&sx[k*68 + ty*4];
            float4 b4 = *(const float4*)&sy[k*68 + tx*4];
            acc[0][0] += a4.x*b4.x; acc[0][1] += a4.x*b4.y; acc[0][2] += a4.x*b4.z; acc[0][3] += a4.x*b4.w;
            acc[1][0] += a4.y*b4.x; acc[1][1] += a4.y*b4.y; acc[1][2] += a4.y*b4.z; acc[1][3] += a4.y*b4.w;
            acc[2][0] += a4.z*b4.x; acc[2][1] += a4.z*b4.y; acc[2][2] += a4.z*b4.z; acc[2][3] += a4.z*b4.w;
            acc[3][0] += a4.w*b4.x; acc[3][1] += a4.w*b4.y; acc[3][2] += a4.w*b4.z; acc[3][3] += a4.w*b4.w;
        }
    }
    if (I0 == J0) {
#pragma unroll
        for (int rr = 0; rr < 4; rr++) {
            int dd = ty*4 + rr - tx*4;
            if (dd >= 0 && dd < 4) pos[I0 + ty*4 + rr] = acc[rr][dd];
        }
    }
    float e[4][4];
#pragma unroll
    for (int rr = 0; rr < 4; rr++) {
        float rl = 0.f;
#pragma unroll
        for (int cc = 0; cc < 4; cc++) {
            e[rr][cc] = expf((acc[rr][cc] - 1.f) * TINV);
            rl += e[rr][cc];
        }
#pragma unroll
        for (int o = 8; o; o >>= 1) rl += __shfl_xor_sync(0xffffffffu, rl, o);
        if (tx == 0) rowp[(size_t)blockIdx.x * n + I0 + ty*4 + rr] = rl;
    }
#pragma unroll
    for (int cc = 0; cc < 4; cc++)
        cbuf[ty][tx*4 + cc] = e[0][cc] + e[1][cc] + e[2][cc] + e[3][cc];
    __syncthreads();
    if (t < 64) {
        float s = 0.f;
#pragma unroll
        for (int y = 0; y < 16; y++) s += cbuf[y][t];
        colp[(size_t)blockIdx.y * n + J0 + t] = s;
    }
}

// rank[i] = #{j: s_j > s_i} + #{j<i: s_j == s_i}; permutation -> direct slot write.
__global__ void rank_kernel() {
    int i = blockIdx.x, t = threadIdx.x;
    float si = g_scores[i];
    int c = 0;
    for (int j = t; j < Nn; j += 256) {
        float sj = g_scores[j];
        c += (sj > si) || (sj == si && j < i);
    }
    __shared__ int rb[256];
    rb[t] = c; __syncthreads();
    for (int s = 128; s; s >>= 1) { if (t < s) rb[t] += rb[t + s]; __syncthreads(); }
    if (t == 0) {
        int r = rb[0];
        if (r < Kp) { g_selidx[r] = i; g_selval[r] = si; }
    }
}

// new_h = f_g[idx] * val. grid Kp, 128 thr.
__global__ void gather_kernel() {
    int p = blockIdx.x, d = threadIdx.x;
    int i = g_selidx[p];
    float v = g_selval[p];
    g_nht[(size_t)p * Dd + d] = g_fgt[(size_t)i * Dd + d] * v;
    g_nhs[(size_t)p * Dd + d] = g_fgs[(size_t)i * Dd + d] * v;
}

// sub[p][q] = rows idx_p, idx_q of A intersect. grid (16,16), 256 thr. uint4 loads.
__global__ void subbits_kernel() {
    __shared__ __align__(16) unsigned pr[64*68];
    __shared__ __align__(16) unsigned qr[64*68];
    __shared__ unsigned pb[64][2];
    int t = threadIdx.x;
    int P0 = blockIdx.y * 64, Q0 = blockIdx.x * 64;
    for (int u = t; u < 1024; u += 256) {
        int r = u >> 4, w4 = u & 15;
        *(uint4*)&pr[r*68 + w4*4] = *(const uint4*)&g_Abits[(size_t)g_selidx[P0 + r] * 64 + w4*4];
        *(uint4*)&qr[r*68 + w4*4] = *(const uint4*)&g_Abits[(size_t)g_selidx[Q0 + r] * 64 + w4*4];
    }
    if (t < 128) ((unsigned*)pb)[t] = 0;
    __syncthreads();
    int p = t >> 2, qb = t & 3;
    unsigned anyv[16];
#pragma unroll
    for (int qq = 0; qq < 16; qq++) anyv[qq] = 0;
    for (int w4 = 0; w4 < 16; w4++) {
        uint4 a = *(const uint4*)&pr[p*68 + w4*4];
#pragma unroll
        for (int qq = 0; qq < 16; qq++) {
            uint4 bv = *(const uint4*)&qr[(qb*16 + qq)*68 + w4*4];
            anyv[qq] |= (a.x & bv.x) | (a.y & bv.y) | (a.z & bv.z) | (a.w & bv.w);
        }
    }
    unsigned res = 0;
#pragma unroll
    for (int qq = 0; qq < 16; qq++) res |= (anyv[qq] ? 1u : 0u) << qq;
    atomicOr(&pb[p][qb >> 1], res << ((qb & 1) * 16));
    __syncthreads();
    if (t < 128) g_Pbits[(size_t)(P0 + (t >> 1)) * 32 + (Q0 >> 5) + (t & 1)] = pb[t >> 1][t & 1];
}

__global__ void dinvp_kernel() {
    int p = blockIdx.x * blockDim.x + threadIdx.x;
    if (p >= Kp) return;
    const uint4* q = (const uint4*)&g_Pbits[(size_t)p * 32];
    int dg = 0;
#pragma unroll
    for (int w = 0; w < 8; w++) { uint4 v = q[w];
        dg += __popc(v.x) + __popc(v.y) + __popc(v.z) + __popc(v.w); }
    g_dinvp[p] = rsqrtf((float)dg);
}

// terms + final reduce, single block 1024 thr.
__global__ void final_kernel(float* __restrict__ out) {
    int t = threadIdx.x;
    float s1 = 0.f, s2 = 0.f;
    for (int i = t; i < Nn; i += 1024) {
        float rs = 0.f, cs = 0.f;
        for (int k = 0; k < 32; k++) { rs += g_rowp1[(size_t)k * Nn + i]; cs += g_colp1[(size_t)k * Nn + i]; }
        s1 += logf(rs) + logf(cs) + 2.f * (1.f - g_pos1[i]) * TINV;
    }
    for (int i = t; i < Kp; i += 1024) {
        float rs = 0.f, cs = 0.f;
        for (int k = 0; k < 16; k++) { rs += g_rowp2[(size_t)k * Kp + i]; cs += g_colp2[(size_t)k * Kp + i]; }
        s2 += logf(rs) + logf(cs) + 2.f * (1.f - g_pos2[i]) * TINV;
    }
    __shared__ float r1[1024], r2[1024];
    r1[t] = s1; r2[t] = s2; __syncthreads();
    for (int s = 512; s; s >>= 1) { if (t < s) { r1[t] += r1[t + s]; r2[t] += r2[t + s]; } __syncthreads(); }
    if (t == 0) out[0] = r1[0] / (float)Nn + r2[0] / (float)Kp;
}

// ----------------- launch -----------------

template <typename T> static T* sym(const T& s) {
    void* p = nullptr;
    cudaGetSymbolAddress(&p, s);
    return (T*)p;
}

extern "C" void kernel_launch(void* const* d_in, const int* in_sizes, int n_in,
                              void* d_out, int out_size) {
    const float* fs  = (const float*)d_in[0];
    const float* ft  = (const float*)d_in[1];
    const float* We  = (const float*)d_in[2];
    const float* be  = (const float*)d_in[3];
    const float* Wg  = (const float*)d_in[4];
    const float* bg  = (const float*)d_in[5];
    const float* Wp  = (const float*)d_in[6];
    const float* bp  = (const float*)d_in[7];
    const float* Wgp = (const float*)d_in[8];
    const float* bgp = (const float*)d_in[9];
    float* out = (float*)d_out;

    float* fes = (float*)sym(g_fes);   float* fet = (float*)sym(g_fet);
    float* h1t = (float*)sym(g_h1t);   float* h1s = (float*)sym(g_h1s);
    float* h2t = (float*)sym(g_h2t);   float* h2s = (float*)sym(g_h2s);
    float* fgt = (float*)sym(g_fgt);   float* fgs = (float*)sym(g_fgs);
    float* nht = (float*)sym(g_nht);   float* nhs = (float*)sym(g_nhs);
    float* ph1t = (float*)sym(g_ph1t); float* ph1s = (float*)sym(g_ph1s);
    float* fpt = (float*)sym(g_fpt);   float* fps = (float*)sym(g_fps);
    float* dinv = (float*)sym(g_dinv); float* dinvp = (float*)sym(g_dinvp);
    unsigned* Ab = (unsigned*)sym(g_Abits);
    unsigned* Pb = (unsigned*)sym(g_Pbits);
    float* Mf = (float*)sym(g_Mf);     float* Pf = (float*)sym(g_Pf);
    float* pp = (float*)sym(g_pp);
    float* rowp1 = (float*)sym(g_rowp1); float* colp1 = (float*)sym(g_colp1);
    float* rowp2 = (float*)sym(g_rowp2); float* colp2 = (float*)sym(g_colp2);
    float* pos1 = (float*)sym(g_pos1);   float* pos2 = (float*)sym(g_pos2);

    embed_kernel<<<dim3(Nn/16, 2), 128>>>(fs, ft, We, be);
    gramA_kernel<<<528, 256>>>();
    dinv_kernel<<<8, 256>>>();
    build_mf<<<Nn*64/256, 256>>>(Ab, dinv, Mf, Nn, 64);
    prop_mma<<<dim3(32, 1, 8), 256>>>(Mf, fet, fes, pp, Nn, 4);
    prop_combine2<<<dim3(256, 2), 256>>>(h1t, h1s, Nn, 4);
    prop_mma<<<dim3(32, 1, 8), 256>>>(Mf, h1t, h1s, pp, Nn, 4);
    prop_combine2<<<dim3(256, 2), 256>>>(h2t, h2s, Nn, 4);
    lin_kernel<<<dim3(Nn/16, 2), 128>>>(fet, h1t, h2t, fes, h1s, h2s, 3, Wg, bg, fgt, fgs, Wp, bp, 1);
    gramnce_kernel<<<dim3(32, 32), 256>>>(fgt, fgs, rowp1, colp1, pos1, Nn);
    rank_kernel<<<Nn, 256>>>();
    gather_kernel<<<Kp, 128>>>();
    subbits_kernel<<<dim3(16, 16), 256>>>();
    dinvp_kernel<<<4, 256>>>();
    build_mf<<<Kp*32/256, 256>>>(Pb, dinvp, Pf, Kp, 32);
    prop_mma<<<dim3(16, 1, 8), 256>>>(Pf, nht, nhs, pp, Kp, 4);
    prop_combine2<<<dim3(128, 2), 256>>>(ph1t, ph1s, Kp, 4);
    lin_kernel<<<dim3(Kp/16, 2), 128>>>(nht, ph1t, nullptr, nhs, ph1s, nullptr, 2, Wgp, bgp, fpt, fps, nullptr, nullptr, 0);
    gramnce_kernel<<<dim3(16, 16), 256>>>(fpt, fps, rowp2, colp2, pos2, Kp);
    final_kernel<<<1, 1024>>>(out);
}

// round 11
// speedup vs baseline: 1.1386x; 1.1386x over previous
#include <cuda_runtime.h>
#include <mma.h>
#include <cstdint>

using namespace nvcuda;

#define Nn 2048
#define Dd 128
#define Cc 512
#define Kp 1024
#define TINV 14.285714285714286f
#define APAD 36
#define BPAD 132

// ----------------- scratch (device globals; allocation-free) -----------------
__device__ float    g_fes[Nn*Dd], g_fet[Nn*Dd];
__device__ unsigned g_Abits[Nn*64];
__device__ float    g_dinv[Nn];
__device__ float    g_Mf[Nn*Nn];              // 16 MB dense masked-normalized adjacency (tf32-rounded)
__device__ float    g_h1t[Nn*Dd], g_h1s[Nn*Dd], g_h2t[Nn*Dd], g_h2s[Nn*Dd];
__device__ float    g_fgt[Nn*Dd], g_fgs[Nn*Dd];
__device__ float    g_pp[2*8*Nn*Dd];          // 16 MB partial-prop scratch
__device__ float    g_rowp1[32*Nn], g_colp1[32*Nn];
__device__ float    g_pos1[Nn];
__device__ float    g_scores[Nn];
__device__ int      g_selidx[Kp];
__device__ float    g_selval[Kp];
__device__ float    g_nht[Kp*Dd], g_nhs[Kp*Dd];
__device__ unsigned g_Pbits[Kp*32];
__device__ float    g_dinvp[Kp];
__device__ float    g_Pf[Kp*Kp];              // 4 MB pooled adjacency (tf32-rounded)
__device__ float    g_ph1t[Kp*Dd], g_ph1s[Kp*Dd];
__device__ float    g_fpt[Kp*Dd], g_fps[Kp*Dd];
__device__ float    g_rowp2[16*Kp], g_colp2[16*Kp];
__device__ float    g_pos2[Kp];

// ----------------- kernels -----------------

// OUT[16 rows] = l2norm(X @ W_embed + b). grid (Nn/16, 2): y=0 fs->fes, y=1 ft->fet. 128 thr.
__global__ void embed_kernel(const float* __restrict__ fs, const float* __restrict__ ft,
                             const float* __restrict__ W, const float* __restrict__ b) {
    const float* X = blockIdx.y ? ft : fs;
    float* OUT = blockIdx.y ? g_fet : g_fes;
    int d = threadIdx.x;
    int R0 = blockIdx.x * 16;
    __shared__ __align__(16) float srow[16][64];
    __shared__ float sW[64][Dd];
    __shared__ float sred[16][132];
    __shared__ float sscale[16];
    float acc[16];
#pragma unroll
    for (int r = 0; r < 16; r++) acc[r] = 0.f;
    for (int kc = 0; kc < Cc; kc += 64) {
        __syncthreads();
        for (int u = d; u < 256; u += Dd) { int r = u >> 4, kq = u & 15;
            ((float4*)srow[r])[kq] = *(const float4*)&X[(size_t)(R0 + r) * Cc + kc + kq*4]; }
        for (int k = 0; k < 64; k++) sW[k][d] = W[(size_t)(kc + k) * Dd + d];
        __syncthreads();
#pragma unroll 4
        for (int k4 = 0; k4 < 16; k4++) {
            float w0 = sW[k4*4+0][d], w1 = sW[k4*4+1][d], w2 = sW[k4*4+2][d], w3 = sW[k4*4+3][d];
#pragma unroll
            for (int r = 0; r < 16; r++) {
                float4 s4 = ((float4*)srow[r])[k4];
                acc[r] += s4.x*w0; acc[r] += s4.y*w1; acc[r] += s4.z*w2; acc[r] += s4.w*w3;
            }
        }
    }
    float bb = b[d];
#pragma unroll
    for (int r = 0; r < 16; r++) sred[r][d] = acc[r] + bb;
    __syncthreads();
    int lane = d & 31, w = d >> 5;
#pragma unroll
    for (int m = 0; m < 4; m++) {
        int r = w*4 + m;
        float x0 = sred[r][lane], x1 = sred[r][lane+32], x2 = sred[r][lane+64], x3 = sred[r][lane+96];
        float s = x0*x0 + x1*x1 + x2*x2 + x3*x3;
#pragma unroll
        for (int o = 16; o; o >>= 1) s += __shfl_xor_sync(0xffffffffu, s, o);
        if (lane == 0) sscale[r] = rsqrtf(s);
    }
    __syncthreads();
#pragma unroll
    for (int r = 0; r < 16; r++) OUT[(size_t)(R0 + r) * Dd + d] = sred[r][d] * sscale[r];
}

// TAGConv linear + l2norm (+ optional scores on teacher branch). grid (n/16, 2), 128 thr.
__global__ void lin_kernel(const float* __restrict__ X0t, const float* __restrict__ X1t,
                           const float* __restrict__ X2t,
                           const float* __restrict__ X0s, const float* __restrict__ X1s,
                           const float* __restrict__ X2s,
                           int nparts, const float* __restrict__ W, const float* __restrict__ b,
                           float* __restrict__ OUTt, float* __restrict__ OUTs,
                           const float* __restrict__ Wp, const float* __restrict__ bp,
                           int do_score) {
    const float* Xs[3];
    float* OUT;
    if (blockIdx.y) { Xs[0] = X0s; Xs[1] = X1s; Xs[2] = X2s; OUT = OUTs; }
    else            { Xs[0] = X0t; Xs[1] = X1t; Xs[2] = X2t; OUT = OUTt; }
    int d = threadIdx.x;
    int R0 = blockIdx.x * 16;
    __shared__ __align__(16) float srow[16][64];
    __shared__ float sW[64][Dd];
    __shared__ float sred[16][132];
    __shared__ float sscale[16];
    float acc[16];
#pragma unroll
    for (int r = 0; r < 16; r++) acc[r] = 0.f;
    int K = nparts * Dd;
    for (int kc = 0; kc < K; kc += 64) {
        const float* Xp = Xs[kc >> 7];
        int off = kc & 127;
        __syncthreads();
        for (int u = d; u < 256; u += Dd) { int r = u >> 4, kq = u & 15;
            ((float4*)srow[r])[kq] = *(const float4*)&Xp[(size_t)(R0 + r) * Dd + off + kq*4]; }
        for (int k = 0; k < 64; k++) sW[k][d] = W[(size_t)(kc + k) * Dd + d];
        __syncthreads();
#pragma unroll 4
        for (int k4 = 0; k4 < 16; k4++) {
            float w0 = sW[k4*4+0][d], w1 = sW[k4*4+1][d], w2 = sW[k4*4+2][d], w3 = sW[k4*4+3][d];
#pragma unroll
            for (int r = 0; r < 16; r++) {
                float4 s4 = ((float4*)srow[r])[k4];
                acc[r] += s4.x*w0; acc[r] += s4.y*w1; acc[r] += s4.z*w2; acc[r] += s4.w*w3;
            }
        }
    }
    float bb = b[d];
#pragma unroll
    for (int r = 0; r < 16; r++) sred[r][d] = acc[r] + bb;
    __syncthreads();
    int lane = d & 31, w = d >> 5;
    bool sc = do_score && (blockIdx.y == 0);
    float wp0 = 0.f, wp1 = 0.f, wp2 = 0.f, wp3 = 0.f;
    if (sc) { wp0 = Wp[lane]; wp1 = Wp[lane+32]; wp2 = Wp[lane+64]; wp3 = Wp[lane+96]; }
#pragma unroll
    for (int m = 0; m < 4; m++) {
        int r = w*4 + m;
        float x0 = sred[r][lane], x1 = sred[r][lane+32], x2 = sred[r][lane+64], x3 = sred[r][lane+96];
        float s = x0*x0 + x1*x1 + x2*x2 + x3*x3;
        float sp = x0*wp0 + x1*wp1 + x2*wp2 + x3*wp3;
#pragma unroll
        for (int o = 16; o; o >>= 1) { s += __shfl_xor_sync(0xffffffffu, s, o);
                                       sp += __shfl_xor_sync(0xffffffffu, sp, o); }
        if (lane == 0) {
            float scale = rsqrtf(s);
            sscale[r] = scale;
            if (sc) g_scores[R0 + r] = 1.f / (1.f + expf(-(sp * scale + bp[0])));
        }
    }
    __syncthreads();
#pragma unroll
    for (int r = 0; r < 16; r++) OUT[(size_t)(R0 + r) * Dd + d] = sred[r][d] * sscale[r];
}

// A = (fet @ fet^T > 0) with forced diag -> bitmask. Symmetric: lower-triangle tiles, mirrored.
__global__ void gramA_kernel() {
    int l = blockIdx.x;
    int by = (int)((sqrtf(8.f * l + 1.f) - 1.f) * 0.5f);
    while ((by + 1) * (by + 2) / 2 <= l) by++;
    while (by * (by + 1) / 2 > l) by--;
    int bx = l - by * (by + 1) / 2;
    int I0 = by * 64, J0 = bx * 64;
    __shared__ __align__(16) float sx[64*68];
    __shared__ __align__(16) float sy[64*68];
    __shared__ unsigned sbits[64][2], tbits[64][2];
    int t = threadIdx.x, tx = t & 15, ty = t >> 4;
    float acc[4][4];
#pragma unroll
    for (int a = 0; a < 4; a++)
#pragma unroll
        for (int c = 0; c < 4; c++) acc[a][c] = 0.f;
    for (int kc = 0; kc < Dd; kc += 64) {
        __syncthreads();
        for (int u = t; u < 4096; u += 256) { int k = u & 63, r = u >> 6;
            sx[k*68 + r] = g_fet[(size_t)(I0 + r) * Dd + kc + k];
            sy[k*68 + r] = g_fet[(size_t)(J0 + r) * Dd + kc + k]; }
        __syncthreads();
#pragma unroll 8
        for (int k = 0; k < 64; k++) {
            float4 a4 = *(const float4*)&sx[k*68 + ty*4];
            float4 b4 = *(const float4*)&sy[k*68 + tx*4];
            acc[0][0] += a4.x*b4.x; acc[0][1] += a4.x*b4.y; acc[0][2] += a4.x*b4.z; acc[0][3] += a4.x*b4.w;
            acc[1][0] += a4.y*b4.x; acc[1][1] += a4.y*b4.y; acc[1][2] += a4.y*b4.z; acc[1][3] += a4.y*b4.w;
            acc[2][0] += a4.z*b4.x; acc[2][1] += a4.z*b4.y; acc[2][2] += a4.z*b4.z; acc[2][3] += a4.z*b4.w;
            acc[3][0] += a4.w*b4.x; acc[3][1] += a4.w*b4.y; acc[3][2] += a4.w*b4.z; acc[3][3] += a4.w*b4.w;
        }
    }
    __syncthreads();
    if (t < 128) { ((unsigned*)sbits)[t] = 0; ((unsigned*)tbits)[t] = 0; }
    __syncthreads();
    int wj = (tx * 4) >> 5, shj = (tx * 4) & 31;
    int wi = (ty * 4) >> 5, shi = (ty * 4) & 31;
#pragma unroll
    for (int rr = 0; rr < 4; rr++) {
        int i = I0 + ty*4 + rr;
        unsigned nib = 0;
#pragma unroll
        for (int cc = 0; cc < 4; cc++) {
            int j = J0 + tx*4 + cc;
            if (acc[rr][cc] > 0.f || i == j) nib |= 1u << cc;
        }
        if (nib) atomicOr(&sbits[ty*4 + rr][wj], nib << shj);
    }
#pragma unroll
    for (int cc = 0; cc < 4; cc++) {
        int j = J0 + tx*4 + cc;
        unsigned nib = 0;
#pragma unroll
        for (int rr = 0; rr < 4; rr++) {
            int i = I0 + ty*4 + rr;
            if (acc[rr][cc] > 0.f || i == j) nib |= 1u << rr;
        }
        if (nib) atomicOr(&tbits[tx*4 + cc][wi], nib << shi);
    }
    __syncthreads();
    if (t < 128) {
        int il = t >> 1, ww = t & 1;
        g_Abits[(size_t)(I0 + il) * 64 + (J0 >> 5) + ww] = sbits[il][ww];
        g_Abits[(size_t)(J0 + il) * 64 + (I0 >> 5) + ww] = tbits[il][ww];
    }
}

__global__ void dinv_kernel() {
    int i = blockIdx.x * blockDim.x + threadIdx.x;
    if (i >= Nn) return;
    const uint4* p = (const uint4*)&g_Abits[(size_t)i * 64];
    int dg = 0;
#pragma unroll
    for (int w = 0; w < 16; w++) { uint4 v = p[w];
        dg += __popc(v.x) + __popc(v.y) + __popc(v.z) + __popc(v.w); }
    g_dinv[i] = rsqrtf((float)dg);
}

// Mf[i,j] = bit(i,j) ? tf32(dinv_i*dinv_j) : 0. One thread per float4 of Mf (MLP-rich).
__global__ void build_mf2(const unsigned* __restrict__ bits, const float* __restrict__ dinv,
                          float* __restrict__ Mf, int n, int nwords) {
    int idx = blockIdx.x * blockDim.x + threadIdx.x;   // float4 index
    int nq = n >> 2;
    if (idx >= n * nq) return;
    int i = idx / nq, q4 = idx - i * nq;               // q4: column group of 4
    unsigned word = bits[(size_t)i * nwords + (q4 >> 3)];
    int sh = (q4 & 7) * 4;
    float di = dinv[i];
    float4 dv = *(const float4*)&dinv[q4 * 4];
    float4 r;
    r.x = (word >> (sh+0)) & 1 ? wmma::__float_to_tf32(di * dv.x) : 0.f;
    r.y = (word >> (sh+1)) & 1 ? wmma::__float_to_tf32(di * dv.y) : 0.f;
    r.z = (word >> (sh+2)) & 1 ? wmma::__float_to_tf32(di * dv.z) : 0.f;
    r.w = (word >> (sh+3)) & 1 ? wmma::__float_to_tf32(di * dv.w) : 0.f;
    *(float4*)&Mf[(size_t)i * n + q4 * 4] = r;
}

// partial = Mf[i-tile, jchunk] @ H[jchunk, :] via smem-staged tf32 wmma.
// grid (n/128, 2*ns); 256 thr = 8 warps (4 m x 2 n), each warp 32x64 out (2x4 frags).
__global__ void __launch_bounds__(256) prop_mma2(
        const float* __restrict__ Mf,
        const float* __restrict__ Ht, const float* __restrict__ Hs,
        float* __restrict__ pp, int n, int ns) {
    int z = blockIdx.y;
    int ts = z / ns, split = z - ts * ns;
    const float* H = ts ? Hs : Ht;
    int i0 = blockIdx.x * 128;
    int chunk = n / ns, jb = split * chunk;
    __shared__ __align__(16) float As[128 * APAD];
    __shared__ __align__(16) float Bs[32 * BPAD];
    int tid = threadIdx.x;
    int warp = tid >> 5, wm = warp & 3, wn = warp >> 2;
    wmma::fragment<wmma::accumulator, 16, 16, 8, float> c[2][4];
#pragma unroll
    for (int mi = 0; mi < 2; mi++)
#pragma unroll
        for (int ni = 0; ni < 4; ni++) wmma::fill_fragment(c[mi][ni], 0.f);
    wmma::fragment<wmma::matrix_a, 16, 16, 8, wmma::precision::tf32, wmma::row_major> af[2];
    wmma::fragment<wmma::matrix_b, 16, 16, 8, wmma::precision::tf32, wmma::row_major> bf[4];
    int arow = tid >> 3, acg = tid & 7;        // As: 32 rows/pass, 8 float4 per row
    int brow = tid >> 5, bcg = tid & 31;       // Bs: 8 rows/pass, 32 float4 per row
    for (int j0 = jb; j0 < jb + chunk; j0 += 32) {
        __syncthreads();
#pragma unroll
        for (int p = 0; p < 4; p++) {
            int r = arow + p * 32;
            *(float4*)&As[r * APAD + acg * 4] =
                *(const float4*)&Mf[(size_t)(i0 + r) * n + j0 + acg * 4];
        }
#pragma unroll
        for (int p = 0; p < 4; p++) {
            int r = brow + p * 8;
            float4 v = *(const float4*)&H[(size_t)(j0 + r) * Dd + bcg * 4];
            v.x = wmma::__float_to_tf32(v.x); v.y = wmma::__float_to_tf32(v.y);
            v.z = wmma::__float_to_tf32(v.z); v.w = wmma::__float_to_tf32(v.w);
            *(float4*)&Bs[r * BPAD + bcg * 4] = v;
        }
        __syncthreads();
#pragma unroll
        for (int kk = 0; kk < 4; kk++) {
#pragma unroll
            for (int mi = 0; mi < 2; mi++)
                wmma::load_matrix_sync(af[mi], &As[(wm*32 + mi*16) * APAD + kk*8], APAD);
#pragma unroll
            for (int ni = 0; ni < 4; ni++)
                wmma::load_matrix_sync(bf[ni], &Bs[(kk*8) * BPAD + wn*64 + ni*16], BPAD);
#pragma unroll
            for (int mi = 0; mi < 2; mi++)
#pragma unroll
                for (int ni = 0; ni < 4; ni++)
                    wmma::mma_sync(c[mi][ni], af[mi], bf[ni], c[mi][ni]);
        }
    }
    float* out = pp + (size_t)(ts * ns + split) * n * Dd;
#pragma unroll
    for (int mi = 0; mi < 2; mi++)
#pragma unroll
        for (int ni = 0; ni < 4; ni++)
            wmma::store_matrix_sync(out + (size_t)(i0 + wm*32 + mi*16) * Dd + wn*64 + ni*16,
                                    c[mi][ni], Dd, wmma::mem_row_major);
}

// O = sum_k partial_k (dinv factors already folded into Mf). grid (n*32/256, 2), 256 thr.
__global__ void prop_combine2(float* __restrict__ Ot, float* __restrict__ Os, int n, int ns) {
    int ts = blockIdx.y;
    float* O = ts ? Os : Ot;
    int idx = blockIdx.x * blockDim.x + threadIdx.x;   // float4 index
    if (idx >= n * 32) return;
    float4 s = make_float4(0.f, 0.f, 0.f, 0.f);
    for (int k = 0; k < ns; k++) {
        float4 v = *(const float4*)&g_pp[(size_t)(ts * ns + k) * n * Dd + (size_t)idx * 4];
        s.x += v.x; s.y += v.y; s.z += v.z; s.w += v.w;
    }
    *(float4*)&O[(size_t)idx * 4] = s;
}

// G = X @ Y^T; per-tile partial row/col sums of exp((G-1)/T); diag tiles emit pos.
__global__ void gramnce_kernel(const float* __restrict__ X, const float* __restrict__ Y,
                               float* __restrict__ rowp, float* __restrict__ colp,
                               float* __restrict__ pos, int n) {
    __shared__ __align__(16) float sx[64*68];
    __shared__ __align__(16) float sy[64*68];
    __shared__ float cbuf[16][64];
    int t = threadIdx.x, tx = t & 15, ty = t >> 4;
    int I0 = blockIdx.y * 64, J0 = blockIdx.x * 64;
    float acc[4][4];
#pragma unroll
    for (int a = 0; a < 4; a++)
#pragma unroll
        for (int c = 0; c < 4; c++) acc[a][c] = 0.f;
    for (int kc = 0; kc < Dd; kc += 64) {
        __syncthreads();
        for (int u = t; u < 4096; u += 256) { int k = u & 63, r = u >> 6;
            sx[k*68 + r] = X[(size_t)(I0 + r) * Dd + kc + k];
            sy[k*68 + r] = Y[(size_t)(J0 + r) * Dd + kc + k]; }
        __syncthreads();
#pragma unroll 8
        for (int k = 0; k < 64; k++) {
            float4 a4 = *(const float4*)&sx[k*68 + ty*4];
            float4 b4 = *(const float4*)&sy[k*68 + tx*4];
            acc[0][0] += a4.x*b4.x; acc[0][1] += a4.x*b4.y; acc[0][2] += a4.x*b4.z; acc[0][3] += a4.x*b4.w;
            acc[1][0] += a4.y*b4.x; acc[1][1] += a4.y*b4.y; acc[1][2] += a4.y*b4.z; acc[1][3] += a4.y*b4.w;
            acc[2][0] += a4.z*b4.x; acc[2][1] += a4.z*b4.y; acc[2][2] += a4.z*b4.z; acc[2][3] += a4.z*b4.w;
            acc[3][0] += a4.w*b4.x; acc[3][1] += a4.w*b4.y; acc[3][2] += a4.w*b4.z; acc[3][3] += a4.w*b4.w;
        }
    }
    if (I0 == J0) {
#pragma unroll
        for (int rr = 0; rr < 4; rr++) {
            int dd = ty*4 + rr - tx*4;
            if (dd >= 0 && dd < 4) pos[I0 + ty*4 + rr] = acc[rr][dd];
        }
    }
    float e[4][4];
#pragma unroll
    for (int rr = 0; rr < 4; rr++) {
        float rl = 0.f;
#pragma unroll
        for (int cc = 0; cc < 4; cc++) {
            e[rr][cc] = expf((acc[rr][cc] - 1.f) * TINV);
            rl += e[rr][cc];
        }
#pragma unroll
        for (int o = 8; o; o >>= 1) rl += __shfl_xor_sync(0xffffffffu, rl, o);
        if (tx == 0) rowp[(size_t)blockIdx.x * n + I0 + ty*4 + rr] = rl;
    }
#pragma unroll
    for (int cc = 0; cc < 4; cc++)
        cbuf[ty][tx*4 + cc] = e[0][cc] + e[1][cc] + e[2][cc] + e[3][cc];
    __syncthreads();
    if (t < 64) {
        float s = 0.f;
#pragma unroll
        for (int y = 0; y < 16; y++) s += cbuf[y][t];
        colp[(size_t)blockIdx.y * n + J0 + t] = s;
    }
}

// rank[i] = #{j: s_j > s_i} + #{j<i: s_j == s_i}; permutation -> direct slot write.
__global__ void rank_kernel() {
    int i = blockIdx.x, t = threadIdx.x;
    float si = g_scores[i];
    int c = 0;
    for (int j = t; j < Nn; j += 256) {
        float sj = g_scores[j];
        c += (sj > si) || (sj == si && j < i);
    }
    __shared__ int rb[256];
    rb[t] = c; __syncthreads();
    for (int s = 128; s; s >>= 1) { if (t < s) rb[t] += rb[t + s]; __syncthreads(); }
    if (t == 0) {
        int r = rb[0];
        if (r < Kp) { g_selidx[r] = i; g_selval[r] = si; }
    }
}

// new_h = f_g[idx] * val. grid Kp, 128 thr.
__global__ void gather_kernel() {
    int p = blockIdx.x, d = threadIdx.x;
    int i = g_selidx[p];
    float v = g_selval[p];
    g_nht[(size_t)p * Dd + d] = g_fgt[(size_t)i * Dd + d] * v;
    g_nhs[(size_t)p * Dd + d] = g_fgs[(size_t)i * Dd + d] * v;
}

// sub[p][q] = rows idx_p, idx_q of A intersect. grid (16,16), 256 thr. uint4 loads.
__global__ void subbits_kernel() {
    __shared__ __align__(16) unsigned pr[64*68];
    __shared__ __align__(16) unsigned qr[64*68];
    __shared__ unsigned pb[64][2];
    int t = threadIdx.x;
    int P0 = blockIdx.y * 64, Q0 = blockIdx.x * 64;
    for (int u = t; u < 1024; u += 256) {
        int r = u >> 4, w4 = u & 15;
        *(uint4*)&pr[r*68 + w4*4] = *(const uint4*)&g_Abits[(size_t)g_selidx[P0 + r] * 64 + w4*4];
        *(uint4*)&qr[r*68 + w4*4] = *(const uint4*)&g_Abits[(size_t)g_selidx[Q0 + r] * 64 + w4*4];
    }
    if (t < 128) ((unsigned*)pb)[t] = 0;
    __syncthreads();
    int p = t >> 2, qb = t & 3;
    unsigned anyv[16];
#pragma unroll
    for (int qq = 0; qq < 16; qq++) anyv[qq] = 0;
    for (int w4 = 0; w4 < 16; w4++) {
        uint4 a = *(const uint4*)&pr[p*68 + w4*4];
#pragma unroll
        for (int qq = 0; qq < 16; qq++) {
            uint4 bv = *(const uint4*)&qr[(qb*16 + qq)*68 + w4*4];
            anyv[qq] |= (a.x & bv.x) | (a.y & bv.y) | (a.z & bv.z) | (a.w & bv.w);
        }
    }
    unsigned res = 0;
#pragma unroll
    for (int qq = 0; qq < 16; qq++) res |= (anyv[qq] ? 1u : 0u) << qq;
    atomicOr(&pb[p][qb >> 1], res << ((qb & 1) * 16));
    __syncthreads();
    if (t < 128) g_Pbits[(size_t)(P0 + (t >> 1)) * 32 + (Q0 >> 5) + (t & 1)] = pb[t >> 1][t & 1];
}

__global__ void dinvp_kernel() {
    int p = blockIdx.x * blockDim.x + threadIdx.x;
    if (p >= Kp) return;
    const uint4* q = (const uint4*)&g_Pbits[(size_t)p * 32];
    int dg = 0;
#pragma unroll
    for (int w = 0; w < 8; w++) { uint4 v = q[w];
        dg += __popc(v.x) + __popc(v.y) + __popc(v.z) + __popc(v.w); }
    g_dinvp[p] = rsqrtf((float)dg);
}

// terms + final reduce, single block 1024 thr.
__global__ void final_kernel(float* __restrict__ out) {
    int t = threadIdx.x;
    float s1 = 0.f, s2 = 0.f;
    for (int i = t; i < Nn; i += 1024) {
        float rs = 0.f, cs = 0.f;
        for (int k = 0; k < 32; k++) { rs += g_rowp1[(size_t)k * Nn + i]; cs += g_colp1[(size_t)k * Nn + i]; }
        s1 += logf(rs) + logf(cs) + 2.f * (1.f - g_pos1[i]) * TINV;
    }
    for (int i = t; i < Kp; i += 1024) {
        float rs = 0.f, cs = 0.f;
        for (int k = 0; k < 16; k++) { rs += g_rowp2[(size_t)k * Kp + i]; cs += g_colp2[(size_t)k * Kp + i]; }
        s2 += logf(rs) + logf(cs) + 2.f * (1.f - g_pos2[i]) * TINV;
    }
    __shared__ float r1[1024], r2[1024];
    r1[t] = s1; r2[t] = s2; __syncthreads();
    for (int s = 512; s; s >>= 1) { if (t < s) { r1[t] += r1[t + s]; r2[t] += r2[t + s]; } __syncthreads(); }
    if (t == 0) out[0] = r1[0] / (float)Nn + r2[0] / (float)Kp;
}

// ----------------- launch -----------------

template <typename T> static T* sym(const T& s) {
    void* p = nullptr;
    cudaGetSymbolAddress(&p, s);
    return (T*)p;
}

extern "C" void kernel_launch(void* const* d_in, const int* in_sizes, int n_in,
                              void* d_out, int out_size) {
    const float* fs  = (const float*)d_in[0];
    const float* ft  = (const float*)d_in[1];
    const float* We  = (const float*)d_in[2];
    const float* be  = (const float*)d_in[3];
    const float* Wg  = (const float*)d_in[4];
    const float* bg  = (const float*)d_in[5];
    const float* Wp  = (const float*)d_in[6];
    const float* bp  = (const float*)d_in[7];
    const float* Wgp = (const float*)d_in[8];
    const float* bgp = (const float*)d_in[9];
    float* out = (float*)d_out;

    float* fes = (float*)sym(g_fes);   float* fet = (float*)sym(g_fet);
    float* h1t = (float*)sym(g_h1t);   float* h1s = (float*)sym(g_h1s);
    float* h2t = (float*)sym(g_h2t);   float* h2s = (float*)sym(g_h2s);
    float* fgt = (float*)sym(g_fgt);   float* fgs = (float*)sym(g_fgs);
    float* nht = (float*)sym(g_nht);   float* nhs = (float*)sym(g_nhs);
    float* ph1t = (float*)sym(g_ph1t); float* ph1s = (float*)sym(g_ph1s);
    float* fpt = (float*)sym(g_fpt);   float* fps = (float*)sym(g_fps);
    float* dinv = (float*)sym(g_dinv); float* dinvp = (float*)sym(g_dinvp);
    unsigned* Ab = (unsigned*)sym(g_Abits);
    unsigned* Pb = (unsigned*)sym(g_Pbits);
    float* Mf = (float*)sym(g_Mf);     float* Pf = (float*)sym(g_Pf);
    float* pp = (float*)sym(g_pp);
    float* rowp1 = (float*)sym(g_rowp1); float* colp1 = (float*)sym(g_colp1);
    float* rowp2 = (float*)sym(g_rowp2); float* colp2 = (float*)sym(g_colp2);
    float* pos1 = (float*)sym(g_pos1);   float* pos2 = (float*)sym(g_pos2);

    embed_kernel<<<dim3(Nn/16, 2), 128>>>(fs, ft, We, be);
    gramA_kernel<<<528, 256>>>();
    dinv_kernel<<<8, 256>>>();
    build_mf2<<<(Nn*(Nn/4) + 255)/256, 256>>>(Ab, dinv, Mf, Nn, 64);
    prop_mma2<<<dim3(16, 16), 256>>>(Mf, fet, fes, pp, Nn, 8);
    prop_combine2<<<dim3(256, 2), 256>>>(h1t, h1s, Nn, 8);
    prop_mma2<<<dim3(16, 16), 256>>>(Mf, h1t, h1s, pp, Nn, 8);
    prop_combine2<<<dim3(256, 2), 256>>>(h2t, h2s, Nn, 8);
    lin_kernel<<<dim3(Nn/16, 2), 128>>>(fet, h1t, h2t, fes, h1s, h2s, 3, Wg, bg, fgt, fgs, Wp, bp, 1);
    gramnce_kernel<<<dim3(32, 32), 256>>>(fgt, fgs, rowp1, colp1, pos1, Nn);
    rank_kernel<<<Nn, 256>>>();
    gather_kernel<<<Kp, 128>>>();
    subbits_kernel<<<dim3(16, 16), 256>>>();
    dinvp_kernel<<<4, 256>>>();
    build_mf2<<<(Kp*(Kp/4) + 255)/256, 256>>>(Pb, dinvp, Pf, Kp, 32);
    prop_mma2<<<dim3(8, 8), 256>>>(Pf, nht, nhs, pp, Kp, 4);
    prop_combine2<<<dim3(128, 2), 256>>>(ph1t, ph1s, Kp, 4);
    lin_kernel<<<dim3(Kp/16, 2), 128>>>(nht, ph1t, nullptr, nhs, ph1s, nullptr, 2, Wgp, bgp, fpt, fps, nullptr, nullptr, 0);
    gramnce_kernel<<<dim3(16, 16), 256>>>(fpt, fps, rowp2, colp2, pos2, Kp);
    final_kernel<<<1, 1024>>>(out);
}

// round 12
// speedup vs baseline: 1.4664x; 1.2879x over previous
#include <cuda_runtime.h>
#include <mma.h>
#include <cuda_fp16.h>
#include <cstdint>

using namespace nvcuda;

#define Nn 2048
#define Dd 128
#define Cc 512
#define Kp 1024
#define TINV 14.285714285714286f
#define APADH 40
#define BPADH 136

// ----------------- scratch (device globals; allocation-free) -----------------
__device__ float    g_fes[Nn*Dd], g_fet[Nn*Dd];
__device__ unsigned g_Abits[Nn*64];
__device__ float    g_dinv[Nn];
__device__ __align__(16) __half g_Mfh[Nn*Nn];   // 8 MB fp16 masked-normalized adjacency
__device__ float    g_h1t[Nn*Dd], g_h1s[Nn*Dd], g_h2t[Nn*Dd], g_h2s[Nn*Dd];
__device__ float    g_fgt[Nn*Dd], g_fgs[Nn*Dd];
__device__ float    g_pp[2*8*Nn*Dd];            // 16 MB partial-prop scratch
__device__ float    g_rowp1[32*Nn], g_colp1[32*Nn];
__device__ float    g_pos1[Nn];
__device__ float    g_scores[Nn];
__device__ int      g_selidx[Kp];
__device__ float    g_selval[Kp];
__device__ float    g_nht[Kp*Dd], g_nhs[Kp*Dd];
__device__ unsigned g_Pbits[Kp*32];
__device__ float    g_dinvp[Kp];
__device__ __align__(16) __half g_Pfh[Kp*Kp];   // 2 MB pooled adjacency fp16
__device__ float    g_ph1t[Kp*Dd], g_ph1s[Kp*Dd];
__device__ float    g_fpt[Kp*Dd], g_fps[Kp*Dd];
__device__ float    g_rowp2[16*Kp], g_colp2[16*Kp];
__device__ float    g_pos2[Kp];

union H8 { uint4 u; __half2 h[4]; };

// ----------------- kernels -----------------

// OUT[16 rows] = l2norm(X @ W_embed + b). grid (Nn/16, 2): y=0 fs->fes, y=1 ft->fet. 128 thr.
__global__ void embed_kernel(const float* __restrict__ fs, const float* __restrict__ ft,
                             const float* __restrict__ W, const float* __restrict__ b) {
    const float* X = blockIdx.y ? ft : fs;
    float* OUT = blockIdx.y ? g_fet : g_fes;
    int d = threadIdx.x;
    int R0 = blockIdx.x * 16;
    __shared__ __align__(16) float srow[16][64];
    __shared__ float sW[64][Dd];
    __shared__ float sred[16][132];
    __shared__ float sscale[16];
    float acc[16];
#pragma unroll
    for (int r = 0; r < 16; r++) acc[r] = 0.f;
    for (int kc = 0; kc < Cc; kc += 64) {
        __syncthreads();
        for (int u = d; u < 256; u += Dd) { int r = u >> 4, kq = u & 15;
            ((float4*)srow[r])[kq] = *(const float4*)&X[(size_t)(R0 + r) * Cc + kc + kq*4]; }
        for (int k = 0; k < 64; k++) sW[k][d] = W[(size_t)(kc + k) * Dd + d];
        __syncthreads();
#pragma unroll 4
        for (int k4 = 0; k4 < 16; k4++) {
            float w0 = sW[k4*4+0][d], w1 = sW[k4*4+1][d], w2 = sW[k4*4+2][d], w3 = sW[k4*4+3][d];
#pragma unroll
            for (int r = 0; r < 16; r++) {
                float4 s4 = ((float4*)srow[r])[k4];
                acc[r] += s4.x*w0; acc[r] += s4.y*w1; acc[r] += s4.z*w2; acc[r] += s4.w*w3;
            }
        }
    }
    float bb = b[d];
#pragma unroll
    for (int r = 0; r < 16; r++) sred[r][d] = acc[r] + bb;
    __syncthreads();
    int lane = d & 31, w = d >> 5;
#pragma unroll
    for (int m = 0; m < 4; m++) {
        int r = w*4 + m;
        float x0 = sred[r][lane], x1 = sred[r][lane+32], x2 = sred[r][lane+64], x3 = sred[r][lane+96];
        float s = x0*x0 + x1*x1 + x2*x2 + x3*x3;
#pragma unroll
        for (int o = 16; o; o >>= 1) s += __shfl_xor_sync(0xffffffffu, s, o);
        if (lane == 0) sscale[r] = rsqrtf(s);
    }
    __syncthreads();
#pragma unroll
    for (int r = 0; r < 16; r++) OUT[(size_t)(R0 + r) * Dd + d] = sred[r][d] * sscale[r];
}

// TAGConv linear + l2norm (+ optional scores on teacher branch). grid (n/16, 2), 128 thr.
__global__ void lin_kernel(const float* __restrict__ X0t, const float* __restrict__ X1t,
                           const float* __restrict__ X2t,
                           const float* __restrict__ X0s, const float* __restrict__ X1s,
                           const float* __restrict__ X2s,
                           int nparts, const float* __restrict__ W, const float* __restrict__ b,
                           float* __restrict__ OUTt, float* __restrict__ OUTs,
                           const float* __restrict__ Wp, const float* __restrict__ bp,
                           int do_score) {
    const float* Xs[3];
    float* OUT;
    if (blockIdx.y) { Xs[0] = X0s; Xs[1] = X1s; Xs[2] = X2s; OUT = OUTs; }
    else            { Xs[0] = X0t; Xs[1] = X1t; Xs[2] = X2t; OUT = OUTt; }
    int d = threadIdx.x;
    int R0 = blockIdx.x * 16;
    __shared__ __align__(16) float srow[16][64];
    __shared__ float sW[64][Dd];
    __shared__ float sred[16][132];
    __shared__ float sscale[16];
    float acc[16];
#pragma unroll
    for (int r = 0; r < 16; r++) acc[r] = 0.f;
    int K = nparts * Dd;
    for (int kc = 0; kc < K; kc += 64) {
        const float* Xp = Xs[kc >> 7];
        int off = kc & 127;
        __syncthreads();
        for (int u = d; u < 256; u += Dd) { int r = u >> 4, kq = u & 15;
            ((float4*)srow[r])[kq] = *(const float4*)&Xp[(size_t)(R0 + r) * Dd + off + kq*4]; }
        for (int k = 0; k < 64; k++) sW[k][d] = W[(size_t)(kc + k) * Dd + d];
        __syncthreads();
#pragma unroll 4
        for (int k4 = 0; k4 < 16; k4++) {
            float w0 = sW[k4*4+0][d], w1 = sW[k4*4+1][d], w2 = sW[k4*4+2][d], w3 = sW[k4*4+3][d];
#pragma unroll
            for (int r = 0; r < 16; r++) {
                float4 s4 = ((float4*)srow[r])[k4];
                acc[r] += s4.x*w0; acc[r] += s4.y*w1; acc[r] += s4.z*w2; acc[r] += s4.w*w3;
            }
        }
    }
    float bb = b[d];
#pragma unroll
    for (int r = 0; r < 16; r++) sred[r][d] = acc[r] + bb;
    __syncthreads();
    int lane = d & 31, w = d >> 5;
    bool sc = do_score && (blockIdx.y == 0);
    float wp0 = 0.f, wp1 = 0.f, wp2 = 0.f, wp3 = 0.f;
    if (sc) { wp0 = Wp[lane]; wp1 = Wp[lane+32]; wp2 = Wp[lane+64]; wp3 = Wp[lane+96]; }
#pragma unroll
    for (int m = 0; m < 4; m++) {
        int r = w*4 + m;
        float x0 = sred[r][lane], x1 = sred[r][lane+32], x2 = sred[r][lane+64], x3 = sred[r][lane+96];
        float s = x0*x0 + x1*x1 + x2*x2 + x3*x3;
        float sp = x0*wp0 + x1*wp1 + x2*wp2 + x3*wp3;
#pragma unroll
        for (int o = 16; o; o >>= 1) { s += __shfl_xor_sync(0xffffffffu, s, o);
                                       sp += __shfl_xor_sync(0xffffffffu, sp, o); }
        if (lane == 0) {
            float scale = rsqrtf(s);
            sscale[r] = scale;
            if (sc) g_scores[R0 + r] = 1.f / (1.f + expf(-(sp * scale + bp[0])));
        }
    }
    __syncthreads();
#pragma unroll
    for (int r = 0; r < 16; r++) OUT[(size_t)(R0 + r) * Dd + d] = sred[r][d] * sscale[r];
}

// A = (fet @ fet^T > 0) with forced diag -> bitmask. Symmetric: lower-triangle tiles, mirrored.
__global__ void gramA_kernel() {
    int l = blockIdx.x;
    int by = (int)((sqrtf(8.f * l + 1.f) - 1.f) * 0.5f);
    while ((by + 1) * (by + 2) / 2 <= l) by++;
    while (by * (by + 1) / 2 > l) by--;
    int bx = l - by * (by + 1) / 2;
    int I0 = by * 64, J0 = bx * 64;
    __shared__ __align__(16) float sx[64*68];
    __shared__ __align__(16) float sy[64*68];
    __shared__ unsigned sbits[64][2], tbits[64][2];
    int t = threadIdx.x, tx = t & 15, ty = t >> 4;
    float acc[4][4];
#pragma unroll
    for (int a = 0; a < 4; a++)
#pragma unroll
        for (int c = 0; c < 4; c++) acc[a][c] = 0.f;
    for (int kc = 0; kc < Dd; kc += 64) {
        __syncthreads();
        for (int u = t; u < 4096; u += 256) { int k = u & 63, r = u >> 6;
            sx[k*68 + r] = g_fet[(size_t)(I0 + r) * Dd + kc + k];
            sy[k*68 + r] = g_fet[(size_t)(J0 + r) * Dd + kc + k]; }
        __syncthreads();
#pragma unroll 8
        for (int k = 0; k < 64; k++) {
            float4 a4 = *(const float4*)&sx[k*68 + ty*4];
            float4 b4 = *(const float4*)&sy[k*68 + tx*4];
            acc[0][0] += a4.x*b4.x; acc[0][1] += a4.x*b4.y; acc[0][2] += a4.x*b4.z; acc[0][3] += a4.x*b4.w;
            acc[1][0] += a4.y*b4.x; acc[1][1] += a4.y*b4.y; acc[1][2] += a4.y*b4.z; acc[1][3] += a4.y*b4.w;
            acc[2][0] += a4.z*b4.x; acc[2][1] += a4.z*b4.y; acc[2][2] += a4.z*b4.z; acc[2][3] += a4.z*b4.w;
            acc[3][0] += a4.w*b4.x; acc[3][1] += a4.w*b4.y; acc[3][2] += a4.w*b4.z; acc[3][3] += a4.w*b4.w;
        }
    }
    __syncthreads();
    if (t < 128) { ((unsigned*)sbits)[t] = 0; ((unsigned*)tbits)[t] = 0; }
    __syncthreads();
    int wj = (tx * 4) >> 5, shj = (tx * 4) & 31;
    int wi = (ty * 4) >> 5, shi = (ty * 4) & 31;
#pragma unroll
    for (int rr = 0; rr < 4; rr++) {
        int i = I0 + ty*4 + rr;
        unsigned nib = 0;
#pragma unroll
        for (int cc = 0; cc < 4; cc++) {
            int j = J0 + tx*4 + cc;
            if (acc[rr][cc] > 0.f || i == j) nib |= 1u << cc;
        }
        if (nib) atomicOr(&sbits[ty*4 + rr][wj], nib << shj);
    }
#pragma unroll
    for (int cc = 0; cc < 4; cc++) {
        int j = J0 + tx*4 + cc;
        unsigned nib = 0;
#pragma unroll
        for (int rr = 0; rr < 4; rr++) {
            int i = I0 + ty*4 + rr;
            if (acc[rr][cc] > 0.f || i == j) nib |= 1u << rr;
        }
        if (nib) atomicOr(&tbits[tx*4 + cc][wi], nib << shi);
    }
    __syncthreads();
    if (t < 128) {
        int il = t >> 1, ww = t & 1;
        g_Abits[(size_t)(I0 + il) * 64 + (J0 >> 5) + ww] = sbits[il][ww];
        g_Abits[(size_t)(J0 + il) * 64 + (I0 >> 5) + ww] = tbits[il][ww];
    }
}

__global__ void dinv_kernel() {
    int i = blockIdx.x * blockDim.x + threadIdx.x;
    if (i >= Nn) return;
    const uint4* p = (const uint4*)&g_Abits[(size_t)i * 64];
    int dg = 0;
#pragma unroll
    for (int w = 0; w < 16; w++) { uint4 v = p[w];
        dg += __popc(v.x) + __popc(v.y) + __popc(v.z) + __popc(v.w); }
    g_dinv[i] = rsqrtf((float)dg);
}

// Mf[i,j] = bit(i,j) ? fp16(dinv_i*dinv_j) : 0. One thread per 8 columns (16B store).
__global__ void build_mfh(const unsigned* __restrict__ bits, const float* __restrict__ dinv,
                          __half* __restrict__ Mf, int n, int nwords) {
    int idx = blockIdx.x * blockDim.x + threadIdx.x;
    int n8 = n >> 3;
    if (idx >= n * n8) return;
    int i = idx / n8, g8 = idx - i * n8;
    unsigned word = bits[(size_t)i * nwords + (g8 >> 2)];
    int sh = (g8 & 3) * 8;
    float di = dinv[i];
    float4 a = *(const float4*)&dinv[g8 * 8];
    float4 c = *(const float4*)&dinv[g8 * 8 + 4];
    H8 o;
    o.h[0] = __floats2half2_rn((word >> (sh+0)) & 1 ? di*a.x : 0.f, (word >> (sh+1)) & 1 ? di*a.y : 0.f);
    o.h[1] = __floats2half2_rn((word >> (sh+2)) & 1 ? di*a.z : 0.f, (word >> (sh+3)) & 1 ? di*a.w : 0.f);
    o.h[2] = __floats2half2_rn((word >> (sh+4)) & 1 ? di*c.x : 0.f, (word >> (sh+5)) & 1 ? di*c.y : 0.f);
    o.h[3] = __floats2half2_rn((word >> (sh+6)) & 1 ? di*c.z : 0.f, (word >> (sh+7)) & 1 ? di*c.w : 0.f);
    *(uint4*)&Mf[(size_t)i * n + g8 * 8] = o.u;
}

// partial = Mf[i-tile, jchunk] @ H[jchunk, :] via smem-staged fp16 wmma (fp32 accumulate).
// grid (n/128, 2*ns); 256 thr = 8 warps (4 m x 2 n), each warp 32x64 out (2x4 frags).
__global__ void __launch_bounds__(256) prop_mma2(
        const __half* __restrict__ Mf,
        const float* __restrict__ Ht, const float* __restrict__ Hs,
        float* __restrict__ pp, int n, int ns) {
    int z = blockIdx.y;
    int ts = z / ns, split = z - ts * ns;
    const float* H = ts ? Hs : Ht;
    int i0 = blockIdx.x * 128;
    int chunk = n / ns, jb = split * chunk;
    __shared__ __align__(16) __half As[128 * APADH];
    __shared__ __align__(16) __half Bs[32 * BPADH];
    int tid = threadIdx.x;
    int warp = tid >> 5, wm = warp & 3, wn = warp >> 2;
    wmma::fragment<wmma::accumulator, 16, 16, 16, float> c[2][4];
#pragma unroll
    for (int mi = 0; mi < 2; mi++)
#pragma unroll
        for (int ni = 0; ni < 4; ni++) wmma::fill_fragment(c[mi][ni], 0.f);
    wmma::fragment<wmma::matrix_a, 16, 16, 16, __half, wmma::row_major> af[2];
    wmma::fragment<wmma::matrix_b, 16, 16, 16, __half, wmma::row_major> bf[4];
    for (int j0 = jb; j0 < jb + chunk; j0 += 32) {
        __syncthreads();
        // As: 128 rows x 32 halves; 512 uint4 tasks, 2 passes
#pragma unroll
        for (int p = 0; p < 2; p++) {
            int task = p * 256 + tid;
            int r = task >> 2, cg = task & 3;
            *(uint4*)&As[r * APADH + cg * 8] =
                *(const uint4*)&Mf[(size_t)(i0 + r) * n + j0 + cg * 8];
        }
        // Bs: 32 rows x 128 halves; 512 tasks of 8 cols, 2 passes
#pragma unroll
        for (int p = 0; p < 2; p++) {
            int task = p * 256 + tid;
            int r = task >> 4, cg = task & 15;
            const float4* src = (const float4*)&H[(size_t)(j0 + r) * Dd + cg * 8];
            float4 v0 = src[0], v1 = src[1];
            H8 o;
            o.h[0] = __floats2half2_rn(v0.x, v0.y);
            o.h[1] = __floats2half2_rn(v0.z, v0.w);
            o.h[2] = __floats2half2_rn(v1.x, v1.y);
            o.h[3] = __floats2half2_rn(v1.z, v1.w);
            *(uint4*)&Bs[r * BPADH + cg * 8] = o.u;
        }
        __syncthreads();
#pragma unroll
        for (int kk = 0; kk < 2; kk++) {
#pragma unroll
            for (int mi = 0; mi < 2; mi++)
                wmma::load_matrix_sync(af[mi], &As[(wm*32 + mi*16) * APADH + kk*16], APADH);
#pragma unroll
            for (int ni = 0; ni < 4; ni++)
                wmma::load_matrix_sync(bf[ni], &Bs[(kk*16) * BPADH + wn*64 + ni*16], BPADH);
#pragma unroll
            for (int mi = 0; mi < 2; mi++)
#pragma unroll
                for (int ni = 0; ni < 4; ni++)
                    wmma::mma_sync(c[mi][ni], af[mi], bf[ni], c[mi][ni]);
        }
    }
    float* out = pp + (size_t)(ts * ns + split) * n * Dd;
#pragma unroll
    for (int mi = 0; mi < 2; mi++)
#pragma unroll
        for (int ni = 0; ni < 4; ni++)
            wmma::store_matrix_sync(out + (size_t)(i0 + wm*32 + mi*16) * Dd + wn*64 + ni*16,
                                    c[mi][ni], Dd, wmma::mem_row_major);
}

// O = sum_k partial_k (dinv factors already folded into Mf). grid (n*32/256, 2), 256 thr.
__global__ void prop_combine2(float* __restrict__ Ot, float* __restrict__ Os, int n, int ns) {
    int ts = blockIdx.y;
    float* O = ts ? Os : Ot;
    int idx = blockIdx.x * blockDim.x + threadIdx.x;   // float4 index
    if (idx >= n * 32) return;
    float4 s = make_float4(0.f, 0.f, 0.f, 0.f);
    for (int k = 0; k < ns; k++) {
        float4 v = *(const float4*)&g_pp[(size_t)(ts * ns + k) * n * Dd + (size_t)idx * 4];
        s.x += v.x; s.y += v.y; s.z += v.z; s.w += v.w;
    }
    *(float4*)&O[(size_t)idx * 4] = s;
}

// G = X @ Y^T; per-tile partial row/col sums of exp((G-1)/T); diag tiles emit pos.
__global__ void gramnce_kernel(const float* __restrict__ X, const float* __restrict__ Y,
                               float* __restrict__ rowp, float* __restrict__ colp,
                               float* __restrict__ pos, int n) {
    __shared__ __align__(16) float sx[64*68];
    __shared__ __align__(16) float sy[64*68];
    __shared__ float cbuf[16][64];
    int t = threadIdx.x, tx = t & 15, ty = t >> 4;
    int I0 = blockIdx.y * 64, J0 = blockIdx.x * 64;
    float acc[4][4];
#pragma unroll
    for (int a = 0; a < 4; a++)
#pragma unroll
        for (int c = 0; c < 4; c++) acc[a][c] = 0.f;
    for (int kc = 0; kc < Dd; kc += 64) {
        __syncthreads();
        for (int u = t; u < 4096; u += 256) { int k = u & 63, r = u >> 6;
            sx[k*68 + r] = X[(size_t)(I0 + r) * Dd + kc + k];
            sy[k*68 + r] = Y[(size_t)(J0 + r) * Dd + kc + k]; }
        __syncthreads();
#pragma unroll 8
        for (int k = 0; k < 64; k++) {
            float4 a4 = *(const float4*)&sx[k*68 + ty*4];
            float4 b4 = *(const float4*)&sy[k*68 + tx*4];
            acc[0][0] += a4.x*b4.x; acc[0][1] += a4.x*b4.y; acc[0][2] += a4.x*b4.z; acc[0][3] += a4.x*b4.w;
            acc[1][0] += a4.y*b4.x; acc[1][1] += a4.y*b4.y; acc[1][2] += a4.y*b4.z; acc[1][3] += a4.y*b4.w;
            acc[2][0] += a4.z*b4.x; acc[2][1] += a4.z*b4.y; acc[2][2] += a4.z*b4.z; acc[2][3] += a4.z*b4.w;
            acc[3][0] += a4.w*b4.x; acc[3][1] += a4.w*b4.y; acc[3][2] += a4.w*b4.z; acc[3][3] += a4.w*b4.w;
        }
    }
    if (I0 == J0) {
#pragma unroll
        for (int rr = 0; rr < 4; rr++) {
            int dd = ty*4 + rr - tx*4;
            if (dd >= 0 && dd < 4) pos[I0 + ty*4 + rr] = acc[rr][dd];
        }
    }
    float e[4][4];
#pragma unroll
    for (int rr = 0; rr < 4; rr++) {
        float rl = 0.f;
#pragma unroll
        for (int cc = 0; cc < 4; cc++) {
            e[rr][cc] = __expf((acc[rr][cc] - 1.f) * TINV);
            rl += e[rr][cc];
        }
#pragma unroll
        for (int o = 8; o; o >>= 1) rl += __shfl_xor_sync(0xffffffffu, rl, o);
        if (tx == 0) rowp[(size_t)blockIdx.x * n + I0 + ty*4 + rr] = rl;
    }
#pragma unroll
    for (int cc = 0; cc < 4; cc++)
        cbuf[ty][tx*4 + cc] = e[0][cc] + e[1][cc] + e[2][cc] + e[3][cc];
    __syncthreads();
    if (t < 64) {
        float s = 0.f;
#pragma unroll
        for (int y = 0; y < 16; y++) s += cbuf[y][t];
        colp[(size_t)blockIdx.y * n + J0 + t] = s;
    }
}

// rank[i] = #{j: s_j > s_i} + #{j<i: s_j == s_i}; permutation -> direct slot write.
__global__ void rank_kernel() {
    int i = blockIdx.x, t = threadIdx.x;
    float si = g_scores[i];
    int c = 0;
    for (int j = t; j < Nn; j += 256) {
        float sj = g_scores[j];
        c += (sj > si) || (sj == si && j < i);
    }
    __shared__ int rb[256];
    rb[t] = c; __syncthreads();
    for (int s = 128; s; s >>= 1) { if (t < s) rb[t] += rb[t + s]; __syncthreads(); }
    if (t == 0) {
        int r = rb[0];
        if (r < Kp) { g_selidx[r] = i; g_selval[r] = si; }
    }
}

// new_h = f_g[idx] * val. grid Kp, 128 thr.
__global__ void gather_kernel() {
    int p = blockIdx.x, d = threadIdx.x;
    int i = g_selidx[p];
    float v = g_selval[p];
    g_nht[(size_t)p * Dd + d] = g_fgt[(size_t)i * Dd + d] * v;
    g_nhs[(size_t)p * Dd + d] = g_fgs[(size_t)i * Dd + d] * v;
}

// sub[p][q] = rows idx_p, idx_q of A intersect. grid (16,16), 256 thr. uint4 loads.
__global__ void subbits_kernel() {
    __shared__ __align__(16) unsigned pr[64*68];
    __shared__ __align__(16) unsigned qr[64*68];
    __shared__ unsigned pb[64][2];
    int t = threadIdx.x;
    int P0 = blockIdx.y * 64, Q0 = blockIdx.x * 64;
    for (int u = t; u < 1024; u += 256) {
        int r = u >> 4, w4 = u & 15;
        *(uint4*)&pr[r*68 + w4*4] = *(const uint4*)&g_Abits[(size_t)g_selidx[P0 + r] * 64 + w4*4];
        *(uint4*)&qr[r*68 + w4*4] = *(const uint4*)&g_Abits[(size_t)g_selidx[Q0 + r] * 64 + w4*4];
    }
    if (t < 128) ((unsigned*)pb)[t] = 0;
    __syncthreads();
    int p = t >> 2, qb = t & 3;
    unsigned anyv[16];
#pragma unroll
    for (int qq = 0; qq < 16; qq++) anyv[qq] = 0;
    for (int w4 = 0; w4 < 16; w4++) {
        uint4 a = *(const uint4*)&pr[p*68 + w4*4];
#pragma unroll
        for (int qq = 0; qq < 16; qq++) {
            uint4 bv = *(const uint4*)&qr[(qb*16 + qq)*68 + w4*4];
            anyv[qq] |= (a.x & bv.x) | (a.y & bv.y) | (a.z & bv.z) | (a.w & bv.w);
        }
    }
    unsigned res = 0;
#pragma unroll
    for (int qq = 0; qq < 16; qq++) res |= (anyv[qq] ? 1u : 0u) << qq;
    atomicOr(&pb[p][qb >> 1], res << ((qb & 1) * 16));
    __syncthreads();
    if (t < 128) g_Pbits[(size_t)(P0 + (t >> 1)) * 32 + (Q0 >> 5) + (t & 1)] = pb[t >> 1][t & 1];
}

__global__ void dinvp_kernel() {
    int p = blockIdx.x * blockDim.x + threadIdx.x;
    if (p >= Kp) return;
    const uint4* q = (const uint4*)&g_Pbits[(size_t)p * 32];
    int dg = 0;
#pragma unroll
    for (int w = 0; w < 8; w++) { uint4 v = q[w];
        dg += __popc(v.x) + __popc(v.y) + __popc(v.z) + __popc(v.w); }
    g_dinvp[p] = rsqrtf((float)dg);
}

// terms + final reduce, single block 1024 thr.
__global__ void final_kernel(float* __restrict__ out) {
    int t = threadIdx.x;
    float s1 = 0.f, s2 = 0.f;
    for (int i = t; i < Nn; i += 1024) {
        float rs = 0.f, cs = 0.f;
        for (int k = 0; k < 32; k++) { rs += g_rowp1[(size_t)k * Nn + i]; cs += g_colp1[(size_t)k * Nn + i]; }
        s1 += __logf(rs) + __logf(cs) + 2.f * (1.f - g_pos1[i]) * TINV;
    }
    for (int i = t; i < Kp; i += 1024) {
        float rs = 0.f, cs = 0.f;
        for (int k = 0; k < 16; k++) { rs += g_rowp2[(size_t)k * Kp + i]; cs += g_colp2[(size_t)k * Kp + i]; }
        s2 += __logf(rs) + __logf(cs) + 2.f * (1.f - g_pos2[i]) * TINV;
    }
    __shared__ float r1[1024], r2[1024];
    r1[t] = s1; r2[t] = s2; __syncthreads();
    for (int s = 512; s; s >>= 1) { if (t < s) { r1[t] += r1[t + s]; r2[t] += r2[t + s]; } __syncthreads(); }
    if (t == 0) out[0] = r1[0] / (float)Nn + r2[0] / (float)Kp;
}

// ----------------- launch -----------------

template <typename T> static T* sym(const T& s) {
    void* p = nullptr;
    cudaGetSymbolAddress(&p, s);
    return (T*)p;
}

extern "C" void kernel_launch(void* const* d_in, const int* in_sizes, int n_in,
                              void* d_out, int out_size) {
    const float* fs  = (const float*)d_in[0];
    const float* ft  = (const float*)d_in[1];
    const float* We  = (const float*)d_in[2];
    const float* be  = (const float*)d_in[3];
    const float* Wg  = (const float*)d_in[4];
    const float* bg  = (const float*)d_in[5];
    const float* Wp  = (const float*)d_in[6];
    const float* bp  = (const float*)d_in[7];
    const float* Wgp = (const float*)d_in[8];
    const float* bgp = (const float*)d_in[9];
    float* out = (float*)d_out;

    float* fes = (float*)sym(g_fes);   float* fet = (float*)sym(g_fet);
    float* h1t = (float*)sym(g_h1t);   float* h1s = (float*)sym(g_h1s);
    float* h2t = (float*)sym(g_h2t);   float* h2s = (float*)sym(g_h2s);
    float* fgt = (float*)sym(g_fgt);   float* fgs = (float*)sym(g_fgs);
    float* nht = (float*)sym(g_nht);   float* nhs = (float*)sym(g_nhs);
    float* ph1t = (float*)sym(g_ph1t); float* ph1s = (float*)sym(g_ph1s);
    float* fpt = (float*)sym(g_fpt);   float* fps = (float*)sym(g_fps);
    float* dinv = (float*)sym(g_dinv); float* dinvp = (float*)sym(g_dinvp);
    unsigned* Ab = (unsigned*)sym(g_Abits);
    unsigned* Pb = (unsigned*)sym(g_Pbits);
    __half* Mfh = (__half*)sym(g_Mfh); __half* Pfh = (__half*)sym(g_Pfh);
    float* pp = (float*)sym(g_pp);
    float* rowp1 = (float*)sym(g_rowp1); float* colp1 = (float*)sym(g_colp1);
    float* rowp2 = (float*)sym(g_rowp2); float* colp2 = (float*)sym(g_colp2);
    float* pos1 = (float*)sym(g_pos1);   float* pos2 = (float*)sym(g_pos2);

    embed_kernel<<<dim3(Nn/16, 2), 128>>>(fs, ft, We, be);
    gramA_kernel<<<528, 256>>>();
    dinv_kernel<<<8, 256>>>();
    build_mfh<<<(Nn*(Nn/8) + 255)/256, 256>>>(Ab, dinv, Mfh, Nn, 64);
    prop_mma2<<<dim3(16, 16), 256>>>(Mfh, fet, fes, pp, Nn, 8);
    prop_combine2<<<dim3(256, 2), 256>>>(h1t, h1s, Nn, 8);
    prop_mma2<<<dim3(16, 16), 256>>>(Mfh, h1t, h1s, pp, Nn, 8);
    prop_combine2<<<dim3(256, 2), 256>>>(h2t, h2s, Nn, 8);
    lin_kernel<<<dim3(Nn/16, 2), 128>>>(fet, h1t, h2t, fes, h1s, h2s, 3, Wg, bg, fgt, fgs, Wp, bp, 1);
    gramnce_kernel<<<dim3(32, 32), 256>>>(fgt, fgs, rowp1, colp1, pos1, Nn);
    rank_kernel<<<Nn, 256>>>();
    gather_kernel<<<Kp, 128>>>();
    subbits_kernel<<<dim3(16, 16), 256>>>();
    dinvp_kernel<<<4, 256>>>();
    build_mfh<<<(Kp*(Kp/8) + 255)/256, 256>>>(Pb, dinvp, Pfh, Kp, 32);
    prop_mma2<<<dim3(8, 8), 256>>>(Pfh, nht, nhs, pp, Kp, 4);
    prop_combine2<<<dim3(128, 2), 256>>>(ph1t, ph1s, Kp, 4);
    lin_kernel<<<dim3(Kp/16, 2), 128>>>(nht, ph1t, nullptr, nhs, ph1s, nullptr, 2, Wgp, bgp, fpt, fps, nullptr, nullptr, 0);
    gramnce_kernel<<<dim3(16, 16), 256>>>(fpt, fps, rowp2, colp2, pos2, Kp);
    final_kernel<<<1, 1024>>>(out);
}

// round 15
// speedup vs baseline: 1.7148x; 1.1694x over previous
#include <cuda_runtime.h>
#include <mma.h>
#include <cuda_fp16.h>
#include <cstdint>

using namespace nvcuda;

#define Nn 2048
#define Dd 128
#define Cc 512
#define Kp 1024
#define TINV 14.285714285714286f
#define APADH 40
#define BPADH 136
#define GPAD 136

// ----------------- scratch (device globals; allocation-free) -----------------
__device__ float    g_fes[Nn*Dd], g_fet[Nn*Dd];
__device__ __align__(16) __half g_fesh[Nn*Dd], g_feth[Nn*Dd];
__device__ unsigned g_Abits[Nn*64];
__device__ float    g_dinv[Nn];
__device__ __align__(16) __half g_Mfh[Nn*Nn];
__device__ float    g_h1t[Nn*Dd], g_h1s[Nn*Dd], g_h2t[Nn*Dd], g_h2s[Nn*Dd];
__device__ __align__(16) __half g_h1th[Nn*Dd], g_h1sh[Nn*Dd];
__device__ float    g_fgt[Nn*Dd], g_fgs[Nn*Dd];
__device__ __align__(16) __half g_fgth[Nn*Dd], g_fgsh[Nn*Dd];
__device__ float    g_pp[2*8*Nn*Dd];
__device__ float    g_rowp1[32*Nn], g_colp1[32*Nn];
__device__ float    g_pos1[Nn];
__device__ float    g_scores[Nn];
__device__ int      g_selidx[Kp];
__device__ float    g_selval[Kp];
__device__ float    g_nht[Kp*Dd], g_nhs[Kp*Dd];
__device__ __align__(16) __half g_nhth[Kp*Dd], g_nhsh[Kp*Dd];
__device__ unsigned g_Pbits[Kp*32];
__device__ float    g_dinvp[Kp];
__device__ __align__(16) __half g_Pfh[Kp*Kp];
__device__ float    g_ph1t[Kp*Dd], g_ph1s[Kp*Dd];
__device__ float    g_fpt[Kp*Dd], g_fps[Kp*Dd];
__device__ __align__(16) __half g_fpth[Kp*Dd], g_fpsh[Kp*Dd];
__device__ float    g_rowp2[16*Kp], g_colp2[16*Kp];
__device__ float    g_pos2[Kp];

union H8 { uint4 u; __half2 h[4]; };

__device__ __forceinline__ void cp16(uint32_t dst, const void* src) {
    asm volatile("cp.async.cg.shared.global [%0], [%1], 16;" :: "r"(dst), "l"(src));
}
__device__ __forceinline__ void cp_commit() { asm volatile("cp.async.commit_group;"); }
template <int N> __device__ __forceinline__ void cp_wait() {
    asm volatile("cp.async.wait_group %0;" :: "n"(N));
}

// ----------------- kernels -----------------

// OUT = l2norm(X @ W_embed + b) + fp16 mirror. grid (Nn/16, 2), 128 thr.
__global__ void embed_kernel(const float* __restrict__ fs, const float* __restrict__ ft,
                             const float* __restrict__ W, const float* __restrict__ b) {
    const float* X = blockIdx.y ? ft : fs;
    float* OUT = blockIdx.y ? g_fet : g_fes;
    __half* OUTH = blockIdx.y ? g_feth : g_fesh;
    int d = threadIdx.x;
    int R0 = blockIdx.x * 16;
    __shared__ __align__(16) float srow[16][64];
    __shared__ float sW[64][Dd];
    __shared__ float sred[16][132];
    __shared__ float sscale[16];
    float acc[16];
#pragma unroll
    for (int r = 0; r < 16; r++) acc[r] = 0.f;
    for (int kc = 0; kc < Cc; kc += 64) {
        __syncthreads();
        for (int u = d; u < 256; u += Dd) { int r = u >> 4, kq = u & 15;
            ((float4*)srow[r])[kq] = *(const float4*)&X[(size_t)(R0 + r) * Cc + kc + kq*4]; }
        for (int k = 0; k < 64; k++) sW[k][d] = W[(size_t)(kc + k) * Dd + d];
        __syncthreads();
#pragma unroll 4
        for (int k4 = 0; k4 < 16; k4++) {
            float w0 = sW[k4*4+0][d], w1 = sW[k4*4+1][d], w2 = sW[k4*4+2][d], w3 = sW[k4*4+3][d];
#pragma unroll
            for (int r = 0; r < 16; r++) {
                float4 s4 = ((float4*)srow[r])[k4];
                acc[r] += s4.x*w0; acc[r] += s4.y*w1; acc[r] += s4.z*w2; acc[r] += s4.w*w3;
            }
        }
    }
    float bb = b[d];
#pragma unroll
    for (int r = 0; r < 16; r++) sred[r][d] = acc[r] + bb;
    __syncthreads();
    int lane = d & 31, w = d >> 5;
#pragma unroll
    for (int m = 0; m < 4; m++) {
        int r = w*4 + m;
        float x0 = sred[r][lane], x1 = sred[r][lane+32], x2 = sred[r][lane+64], x3 = sred[r][lane+96];
        float s = x0*x0 + x1*x1 + x2*x2 + x3*x3;
#pragma unroll
        for (int o = 16; o; o >>= 1) s += __shfl_xor_sync(0xffffffffu, s, o);
        if (lane == 0) sscale[r] = rsqrtf(s);
    }
    __syncthreads();
#pragma unroll
    for (int r = 0; r < 16; r++) {
        float v = sred[r][d] * sscale[r];
        OUT[(size_t)(R0 + r) * Dd + d] = v;
        OUTH[(size_t)(R0 + r) * Dd + d] = __float2half_rn(v);
    }
}

// TAGConv linear + l2norm + fp16 mirror (+ optional scores). grid (n/16, 2), 128 thr.
__global__ void lin_kernel(const float* __restrict__ X0t, const float* __restrict__ X1t,
                           const float* __restrict__ X2t,
                           const float* __restrict__ X0s, const float* __restrict__ X1s,
                           const float* __restrict__ X2s,
                           int nparts, const float* __restrict__ W, const float* __restrict__ b,
                           float* __restrict__ OUTt, float* __restrict__ OUTs,
                           __half* __restrict__ OUTth, __half* __restrict__ OUTsh,
                           const float* __restrict__ Wp, const float* __restrict__ bp,
                           int do_score) {
    const float* Xs[3];
    float* OUT; __half* OUTH;
    if (blockIdx.y) { Xs[0] = X0s; Xs[1] = X1s; Xs[2] = X2s; OUT = OUTs; OUTH = OUTsh; }
    else            { Xs[0] = X0t; Xs[1] = X1t; Xs[2] = X2t; OUT = OUTt; OUTH = OUTth; }
    int d = threadIdx.x;
    int R0 = blockIdx.x * 16;
    __shared__ __align__(16) float srow[16][64];
    __shared__ float sW[64][Dd];
    __shared__ float sred[16][132];
    __shared__ float sscale[16];
    float acc[16];
#pragma unroll
    for (int r = 0; r < 16; r++) acc[r] = 0.f;
    int K = nparts * Dd;
    for (int kc = 0; kc < K; kc += 64) {
        const float* Xp = Xs[kc >> 7];
        int off = kc & 127;
        __syncthreads();
        for (int u = d; u < 256; u += Dd) { int r = u >> 4, kq = u & 15;
            ((float4*)srow[r])[kq] = *(const float4*)&Xp[(size_t)(R0 + r) * Dd + off + kq*4]; }
        for (int k = 0; k < 64; k++) sW[k][d] = W[(size_t)(kc + k) * Dd + d];
        __syncthreads();
#pragma unroll 4
        for (int k4 = 0; k4 < 16; k4++) {
            float w0 = sW[k4*4+0][d], w1 = sW[k4*4+1][d], w2 = sW[k4*4+2][d], w3 = sW[k4*4+3][d];
#pragma unroll
            for (int r = 0; r < 16; r++) {
                float4 s4 = ((float4*)srow[r])[k4];
                acc[r] += s4.x*w0; acc[r] += s4.y*w1; acc[r] += s4.z*w2; acc[r] += s4.w*w3;
            }
        }
    }
    float bb = b[d];
#pragma unroll
    for (int r = 0; r < 16; r++) sred[r][d] = acc[r] + bb;
    __syncthreads();
    int lane = d & 31, w = d >> 5;
    bool sc = do_score && (blockIdx.y == 0);
    float wp0 = 0.f, wp1 = 0.f, wp2 = 0.f, wp3 = 0.f;
    if (sc) { wp0 = Wp[lane]; wp1 = Wp[lane+32]; wp2 = Wp[lane+64]; wp3 = Wp[lane+96]; }
#pragma unroll
    for (int m = 0; m < 4; m++) {
        int r = w*4 + m;
        float x0 = sred[r][lane], x1 = sred[r][lane+32], x2 = sred[r][lane+64], x3 = sred[r][lane+96];
        float s = x0*x0 + x1*x1 + x2*x2 + x3*x3;
        float sp = x0*wp0 + x1*wp1 + x2*wp2 + x3*wp3;
#pragma unroll
        for (int o = 16; o; o >>= 1) { s += __shfl_xor_sync(0xffffffffu, s, o);
                                       sp += __shfl_xor_sync(0xffffffffu, sp, o); }
        if (lane == 0) {
            float scale = rsqrtf(s);
            sscale[r] = scale;
            if (sc) g_scores[R0 + r] = 1.f / (1.f + expf(-(sp * scale + bp[0])));
        }
    }
    __syncthreads();
#pragma unroll
    for (int r = 0; r < 16; r++) {
        float v = sred[r][d] * sscale[r];
        OUT[(size_t)(R0 + r) * Dd + d] = v;
        OUTH[(size_t)(R0 + r) * Dd + d] = __float2half_rn(v);
    }
}

// A = (fet @ fet^T > 0) with forced diag -> bitmask (fp32, graph must be exact).
__global__ void gramA_kernel() {
    int l = blockIdx.x;
    int by = (int)((sqrtf(8.f * l + 1.f) - 1.f) * 0.5f);
    while ((by + 1) * (by + 2) / 2 <= l) by++;
    while (by * (by + 1) / 2 > l) by--;
    int bx = l - by * (by + 1) / 2;
    int I0 = by * 64, J0 = bx * 64;
    __shared__ __align__(16) float sx[64*68];
    __shared__ __align__(16) float sy[64*68];
    __shared__ unsigned sbits[64][2], tbits[64][2];
    int t = threadIdx.x, tx = t & 15, ty = t >> 4;
    float acc[4][4];
#pragma unroll
    for (int a = 0; a < 4; a++)
#pragma unroll
        for (int c = 0; c < 4; c++) acc[a][c] = 0.f;
    for (int kc = 0; kc < Dd; kc += 64) {
        __syncthreads();
        for (int u = t; u < 4096; u += 256) { int k = u & 63, r = u >> 6;
            sx[k*68 + r] = g_fet[(size_t)(I0 + r) * Dd + kc + k];
            sy[k*68 + r] = g_fet[(size_t)(J0 + r) * Dd + kc + k]; }
        __syncthreads();
#pragma unroll 8
        for (int k = 0; k < 64; k++) {
            float4 a4 = *(const float4*)&sx[k*68 + ty*4];
            float4 b4 = *(const float4*)&sy[k*68 + tx*4];
            acc[0][0] += a4.x*b4.x; acc[0][1] += a4.x*b4.y; acc[0][2] += a4.x*b4.z; acc[0][3] += a4.x*b4.w;
            acc[1][0] += a4.y*b4.x; acc[1][1] += a4.y*b4.y; acc[1][2] += a4.y*b4.z; acc[1][3] += a4.y*b4.w;
            acc[2][0] += a4.z*b4.x; acc[2][1] += a4.z*b4.y; acc[2][2] += a4.z*b4.z; acc[2][3] += a4.z*b4.w;
            acc[3][0] += a4.w*b4.x; acc[3][1] += a4.w*b4.y; acc[3][2] += a4.w*b4.z; acc[3][3] += a4.w*b4.w;
        }
    }
    __syncthreads();
    if (t < 128) { ((unsigned*)sbits)[t] = 0; ((unsigned*)tbits)[t] = 0; }
    __syncthreads();
    int wj = (tx * 4) >> 5, shj = (tx * 4) & 31;
    int wi = (ty * 4) >> 5, shi = (ty * 4) & 31;
#pragma unroll
    for (int rr = 0; rr < 4; rr++) {
        int i = I0 + ty*4 + rr;
        unsigned nib = 0;
#pragma unroll
        for (int cc = 0; cc < 4; cc++) {
            int j = J0 + tx*4 + cc;
            if (acc[rr][cc] > 0.f || i == j) nib |= 1u << cc;
        }
        if (nib) atomicOr(&sbits[ty*4 + rr][wj], nib << shj);
    }
#pragma unroll
    for (int cc = 0; cc < 4; cc++) {
        int j = J0 + tx*4 + cc;
        unsigned nib = 0;
#pragma unroll
        for (int rr = 0; rr < 4; rr++) {
            int i = I0 + ty*4 + rr;
            if (acc[rr][cc] > 0.f || i == j) nib |= 1u << rr;
        }
        if (nib) atomicOr(&tbits[tx*4 + cc][wi], nib << shi);
    }
    __syncthreads();
    if (t < 128) {
        int il = t >> 1, ww = t & 1;
        g_Abits[(size_t)(I0 + il) * 64 + (J0 >> 5) + ww] = sbits[il][ww];
        g_Abits[(size_t)(J0 + il) * 64 + (I0 >> 5) + ww] = tbits[il][ww];
    }
}

__global__ void dinv_kernel() {
    int i = blockIdx.x * blockDim.x + threadIdx.x;
    if (i >= Nn) return;
    const uint4* p = (const uint4*)&g_Abits[(size_t)i * 64];
    int dg = 0;
#pragma unroll
    for (int w = 0; w < 16; w++) { uint4 v = p[w];
        dg += __popc(v.x) + __popc(v.y) + __popc(v.z) + __popc(v.w); }
    g_dinv[i] = rsqrtf((float)dg);
}

// Mf[i,j] = bit(i,j) ? fp16(dinv_i*dinv_j) : 0. One thread per 8 cols.
__global__ void build_mfh(const unsigned* __restrict__ bits, const float* __restrict__ dinv,
                          __half* __restrict__ Mf, int n, int nwords) {
    int idx = blockIdx.x * blockDim.x + threadIdx.x;
    int n8 = n >> 3;
    if (idx >= n * n8) return;
    int i = idx / n8, g8 = idx - i * n8;
    unsigned word = bits[(size_t)i * nwords + (g8 >> 2)];
    int sh = (g8 & 3) * 8;
    float di = dinv[i];
    float4 a = *(const float4*)&dinv[g8 * 8];
    float4 c = *(const float4*)&dinv[g8 * 8 + 4];
    H8 o;
    o.h[0] = __floats2half2_rn((word >> (sh+0)) & 1 ? di*a.x : 0.f, (word >> (sh+1)) & 1 ? di*a.y : 0.f);
    o.h[1] = __floats2half2_rn((word >> (sh+2)) & 1 ? di*a.z : 0.f, (word >> (sh+3)) & 1 ? di*a.w : 0.f);
    o.h[2] = __floats2half2_rn((word >> (sh+4)) & 1 ? di*c.x : 0.f, (word >> (sh+5)) & 1 ? di*c.y : 0.f);
    o.h[3] = __floats2half2_rn((word >> (sh+6)) & 1 ? di*c.z : 0.f, (word >> (sh+7)) & 1 ? di*c.w : 0.f);
    *(uint4*)&Mf[(size_t)i * n + g8 * 8] = o.u;
}

// partial = Mf @ H (fp16 mirrors), cp.async double-buffered staging.
// grid (n/128, 2*ns); 256 thr = 8 warps (4m x 2n), each 32x64 out.
__global__ void __launch_bounds__(256) prop_mma3(
        const __half* __restrict__ Mf,
        const __half* __restrict__ Hth, const __half* __restrict__ Hsh,
        float* __restrict__ pp, int n, int ns) {
    int z = blockIdx.y;
    int ts = z / ns, split = z - ts * ns;
    const __half* H = ts ? Hsh : Hth;
    int i0 = blockIdx.x * 128;
    int chunk = n / ns, jb = split * chunk;
    __shared__ __align__(16) __half As[2][128 * APADH];
    __shared__ __align__(16) __half Bs[2][32 * BPADH];
    int tid = threadIdx.x;
    int warp = tid >> 5, wm = warp & 3, wn = warp >> 2;
    int ar = tid >> 1, ag = tid & 1;       // As: 128 rows, 4 granules(8h) per row
    int br = tid >> 4, bg = tid & 15;      // Bs: 16 rows/pass, 16 granules(8h) per row
    wmma::fragment<wmma::accumulator, 16, 16, 16, float> c[2][4];
#pragma unroll
    for (int mi = 0; mi < 2; mi++)
#pragma unroll
        for (int ni = 0; ni < 4; ni++) wmma::fill_fragment(c[mi][ni], 0.f);
    wmma::fragment<wmma::matrix_a, 16, 16, 16, __half, wmma::row_major> af[2];
    wmma::fragment<wmma::matrix_b, 16, 16, 16, __half, wmma::row_major> bf[4];

    int niter = chunk >> 5;
    auto stage = [&](int buf, int j0) {
        uint32_t abase = (uint32_t)__cvta_generic_to_shared(&As[buf][0]);
        uint32_t bbase = (uint32_t)__cvta_generic_to_shared(&Bs[buf][0]);
#pragma unroll
        for (int g = 0; g < 2; g++)
            cp16(abase + (ar * APADH + (ag*2+g) * 8) * 2,
                 &Mf[(size_t)(i0 + ar) * n + j0 + (ag*2+g) * 8]);
#pragma unroll
        for (int p = 0; p < 2; p++)
            cp16(bbase + ((br + p*16) * BPADH + bg * 8) * 2,
                 &H[(size_t)(j0 + br + p*16) * Dd + bg * 8]);
    };

    stage(0, jb);
    cp_commit();
    for (int it = 0; it < niter; it++) {
        int cur = it & 1;
        if (it + 1 < niter) { stage(cur ^ 1, jb + (it + 1) * 32); cp_commit(); cp_wait<1>(); }
        else cp_wait<0>();
        __syncthreads();
#pragma unroll
        for (int kk = 0; kk < 2; kk++) {
#pragma unroll
            for (int mi = 0; mi < 2; mi++)
                wmma::load_matrix_sync(af[mi], &As[cur][(wm*32 + mi*16) * APADH + kk*16], APADH);
#pragma unroll
            for (int ni = 0; ni < 4; ni++)
                wmma::load_matrix_sync(bf[ni], &Bs[cur][(kk*16) * BPADH + wn*64 + ni*16], BPADH);
#pragma unroll
            for (int mi = 0; mi < 2; mi++)
#pragma unroll
                for (int ni = 0; ni < 4; ni++)
                    wmma::mma_sync(c[mi][ni], af[mi], bf[ni], c[mi][ni]);
        }
        __syncthreads();
    }
    float* out = pp + (size_t)(ts * ns + split) * n * Dd;
#pragma unroll
    for (int mi = 0; mi < 2; mi++)
#pragma unroll
        for (int ni = 0; ni < 4; ni++)
            wmma::store_matrix_sync(out + (size_t)(i0 + wm*32 + mi*16) * Dd + wn*64 + ni*16,
                                    c[mi][ni], Dd, wmma::mem_row_major);
}

// O = sum_k partial_k; optional fp16 mirror. grid (n*32/256, 2), 256 thr.
__global__ void prop_combine3(float* __restrict__ Ot, float* __restrict__ Os,
                              __half* __restrict__ Oth, __half* __restrict__ Osh,
                              int n, int ns) {
    int ts = blockIdx.y;
    float* O = ts ? Os : Ot;
    __half* OH = ts ? Osh : Oth;
    int idx = blockIdx.x * blockDim.x + threadIdx.x;
    if (idx >= n * 32) return;
    float4 s = make_float4(0.f, 0.f, 0.f, 0.f);
    for (int k = 0; k < ns; k++) {
        float4 v = *(const float4*)&g_pp[(size_t)(ts * ns + k) * n * Dd + (size_t)idx * 4];
        s.x += v.x; s.y += v.y; s.z += v.z; s.w += v.w;
    }
    *(float4*)&O[(size_t)idx * 4] = s;
    if (OH) {
        __half2 h0 = __floats2half2_rn(s.x, s.y);
        __half2 h1 = __floats2half2_rn(s.z, s.w);
        *(__half2*)&OH[(size_t)idx * 4] = h0;
        *(__half2*)&OH[(size_t)idx * 4 + 2] = h1;
    }
}

// G = Xh @ Yh^T via fp16 wmma; exp/rowsums epilogue; diag tiles emit pos.
// Gs aliases sx (dead after mma) -> static smem 38.9 KB.
// Staging: 64 rows x 128 halves = 16 uint4/row -> 1024 tasks per buffer (4/thread).
// grid (n/64, n/64), 256 thr = 8 warps (4m x 2n), each 16x32 out.
__global__ void __launch_bounds__(256) gramnce_h(
        const __half* __restrict__ Xh, const __half* __restrict__ Yh,
        float* __restrict__ rowp, float* __restrict__ colp,
        float* __restrict__ pos, int n) {
    __shared__ __align__(16) __half sx[64 * GPAD];
    __shared__ __align__(16) __half sy[64 * GPAD];
    __shared__ float cbuf[16][64];
    float* Gs = reinterpret_cast<float*>(sx);   // 64*68 floats = 17408 B = sizeof(sx)
    int t = threadIdx.x, tx = t & 15, ty = t >> 4;
    int warp = t >> 5, wm = warp & 3, wn = warp >> 2;
    int I0 = blockIdx.y * 64, J0 = blockIdx.x * 64;
    int r0 = t >> 4, g0 = t & 15;   // 16 granules of 8 halves cover the 128-half row
#pragma unroll
    for (int p = 0; p < 4; p++) {
        int r = r0 + p * 16;
        *(uint4*)&sx[r * GPAD + g0 * 8] = *(const uint4*)&Xh[(size_t)(I0 + r) * Dd + g0 * 8];
        *(uint4*)&sy[r * GPAD + g0 * 8] = *(const uint4*)&Yh[(size_t)(J0 + r) * Dd + g0 * 8];
    }
    __syncthreads();
    wmma::fragment<wmma::accumulator, 16, 16, 16, float> c[2];
    wmma::fill_fragment(c[0], 0.f);
    wmma::fill_fragment(c[1], 0.f);
    wmma::fragment<wmma::matrix_a, 16, 16, 16, __half, wmma::row_major> af;
    wmma::fragment<wmma::matrix_b, 16, 16, 16, __half, wmma::col_major> bf[2];
#pragma unroll
    for (int k = 0; k < 8; k++) {
        wmma::load_matrix_sync(af, &sx[(wm*16) * GPAD + k*16], GPAD);
#pragma unroll
        for (int ni = 0; ni < 2; ni++)
            wmma::load_matrix_sync(bf[ni], &sy[(wn*32 + ni*16) * GPAD + k*16], GPAD);
        wmma::mma_sync(c[0], af, bf[0], c[0]);
        wmma::mma_sync(c[1], af, bf[1], c[1]);
    }
    __syncthreads();   // all warps done reading sx -> safe to overwrite with Gs
#pragma unroll
    for (int ni = 0; ni < 2; ni++)
        wmma::store_matrix_sync(&Gs[(wm*16) * 68 + wn*32 + ni*16], c[ni], 68, wmma::mem_row_major);
    __syncthreads();
    if (I0 == J0 && t < 64) pos[I0 + t] = Gs[t * 68 + t];
    float e[4][4];
#pragma unroll
    for (int rr = 0; rr < 4; rr++) {
        float rl = 0.f;
#pragma unroll
        for (int cc = 0; cc < 4; cc++) {
            e[rr][cc] = __expf((Gs[(ty*4+rr) * 68 + tx*4 + cc] - 1.f) * TINV);
            rl += e[rr][cc];
        }
#pragma unroll
        for (int o = 8; o; o >>= 1) rl += __shfl_xor_sync(0xffffffffu, rl, o);
        if (tx == 0) rowp[(size_t)blockIdx.x * n + I0 + ty*4 + rr] = rl;
    }
#pragma unroll
    for (int cc = 0; cc < 4; cc++)
        cbuf[ty][tx*4 + cc] = e[0][cc] + e[1][cc] + e[2][cc] + e[3][cc];
    __syncthreads();
    if (t < 64) {
        float s = 0.f;
#pragma unroll
        for (int y = 0; y < 16; y++) s += cbuf[y][t];
        colp[(size_t)blockIdx.y * n + J0 + t] = s;
    }
}

// rank is a permutation -> direct slot write.
__global__ void rank_kernel() {
    int i = blockIdx.x, t = threadIdx.x;
    float si = g_scores[i];
    int c = 0;
    for (int j = t; j < Nn; j += 256) {
        float sj = g_scores[j];
        c += (sj > si) || (sj == si && j < i);
    }
    __shared__ int rb[256];
    rb[t] = c; __syncthreads();
    for (int s = 128; s; s >>= 1) { if (t < s) rb[t] += rb[t + s]; __syncthreads(); }
    if (t == 0) {
        int r = rb[0];
        if (r < Kp) { g_selidx[r] = i; g_selval[r] = si; }
    }
}

// new_h = f_g[idx] * val (+ fp16 mirror). grid Kp, 128 thr.
__global__ void gather_kernel() {
    int p = blockIdx.x, d = threadIdx.x;
    int i = g_selidx[p];
    float v = g_selval[p];
    float a = g_fgt[(size_t)i * Dd + d] * v;
    float b = g_fgs[(size_t)i * Dd + d] * v;
    g_nht[(size_t)p * Dd + d] = a;
    g_nhs[(size_t)p * Dd + d] = b;
    g_nhth[(size_t)p * Dd + d] = __float2half_rn(a);
    g_nhsh[(size_t)p * Dd + d] = __float2half_rn(b);
}

// sub[p][q] = rows idx_p, idx_q of A intersect. grid (16,16), 256 thr.
__global__ void subbits_kernel() {
    __shared__ __align__(16) unsigned pr[64*68];
    __shared__ __align__(16) unsigned qr[64*68];
    __shared__ unsigned pb[64][2];
    int t = threadIdx.x;
    int P0 = blockIdx.y * 64, Q0 = blockIdx.x * 64;
    for (int u = t; u < 1024; u += 256) {
        int r = u >> 4, w4 = u & 15;
        *(uint4*)&pr[r*68 + w4*4] = *(const uint4*)&g_Abits[(size_t)g_selidx[P0 + r] * 64 + w4*4];
        *(uint4*)&qr[r*68 + w4*4] = *(const uint4*)&g_Abits[(size_t)g_selidx[Q0 + r] * 64 + w4*4];
    }
    if (t < 128) ((unsigned*)pb)[t] = 0;
    __syncthreads();
    int p = t >> 2, qb = t & 3;
    unsigned anyv[16];
#pragma unroll
    for (int qq = 0; qq < 16; qq++) anyv[qq] = 0;
    for (int w4 = 0; w4 < 16; w4++) {
        uint4 a = *(const uint4*)&pr[p*68 + w4*4];
#pragma unroll
        for (int qq = 0; qq < 16; qq++) {
            uint4 bv = *(const uint4*)&qr[(qb*16 + qq)*68 + w4*4];
            anyv[qq] |= (a.x & bv.x) | (a.y & bv.y) | (a.z & bv.z) | (a.w & bv.w);
        }
    }
    unsigned res = 0;
#pragma unroll
    for (int qq = 0; qq < 16; qq++) res |= (anyv[qq] ? 1u : 0u) << qq;
    atomicOr(&pb[p][qb >> 1], res << ((qb & 1) * 16));
    __syncthreads();
    if (t < 128) g_Pbits[(size_t)(P0 + (t >> 1)) * 32 + (Q0 >> 5) + (t & 1)] = pb[t >> 1][t & 1];
}

__global__ void dinvp_kernel() {
    int p = blockIdx.x * blockDim.x + threadIdx.x;
    if (p >= Kp) return;
    const uint4* q = (const uint4*)&g_Pbits[(size_t)p * 32];
    int dg = 0;
#pragma unroll
    for (int w = 0; w < 8; w++) { uint4 v = q[w];
        dg += __popc(v.x) + __popc(v.y) + __popc(v.z) + __popc(v.w); }
    g_dinvp[p] = rsqrtf((float)dg);
}

// terms + final reduce, single block 1024 thr.
__global__ void final_kernel(float* __restrict__ out) {
    int t = threadIdx.x;
    float s1 = 0.f, s2 = 0.f;
    for (int i = t; i < Nn; i += 1024) {
        float rs = 0.f, cs = 0.f;
        for (int k = 0; k < 32; k++) { rs += g_rowp1[(size_t)k * Nn + i]; cs += g_colp1[(size_t)k * Nn + i]; }
        s1 += __logf(rs) + __logf(cs) + 2.f * (1.f - g_pos1[i]) * TINV;
    }
    for (int i = t; i < Kp; i += 1024) {
        float rs = 0.f, cs = 0.f;
        for (int k = 0; k < 16; k++) { rs += g_rowp2[(size_t)k * Kp + i]; cs += g_colp2[(size_t)k * Kp + i]; }
        s2 += __logf(rs) + __logf(cs) + 2.f * (1.f - g_pos2[i]) * TINV;
    }
    __shared__ float r1[1024], r2[1024];
    r1[t] = s1; r2[t] = s2; __syncthreads();
    for (int s = 512; s; s >>= 1) { if (t < s) { r1[t] += r1[t + s]; r2[t] += r2[t + s]; } __syncthreads(); }
    if (t == 0) out[0] = r1[0] / (float)Nn + r2[0] / (float)Kp;
}

// ----------------- launch -----------------

template <typename T> static T* sym(const T& s) {
    void* p = nullptr;
    cudaGetSymbolAddress(&p, s);
    return (T*)p;
}

extern "C" void kernel_launch(void* const* d_in, const int* in_sizes, int n_in,
                              void* d_out, int out_size) {
    const float* fs  = (const float*)d_in[0];
    const float* ft  = (const float*)d_in[1];
    const float* We  = (const float*)d_in[2];
    const float* be  = (const float*)d_in[3];
    const float* Wg  = (const float*)d_in[4];
    const float* bg  = (const float*)d_in[5];
    const float* Wp  = (const float*)d_in[6];
    const float* bp  = (const float*)d_in[7];
    const float* Wgp = (const float*)d_in[8];
    const float* bgp = (const float*)d_in[9];
    float* out = (float*)d_out;

    float* fes = (float*)sym(g_fes);   float* fet = (float*)sym(g_fet);
    __half* fesh = (__half*)sym(g_fesh); __half* feth = (__half*)sym(g_feth);
    float* h1t = (float*)sym(g_h1t);   float* h1s = (float*)sym(g_h1s);
    __half* h1th = (__half*)sym(g_h1th); __half* h1sh = (__half*)sym(g_h1sh);
    float* h2t = (float*)sym(g_h2t);   float* h2s = (float*)sym(g_h2s);
    float* fgt = (float*)sym(g_fgt);   float* fgs = (float*)sym(g_fgs);
    __half* fgth = (__half*)sym(g_fgth); __half* fgsh = (__half*)sym(g_fgsh);
    float* nht = (float*)sym(g_nht);   float* nhs = (float*)sym(g_nhs);
    __half* nhth = (__half*)sym(g_nhth); __half* nhsh = (__half*)sym(g_nhsh);
    float* ph1t = (float*)sym(g_ph1t); float* ph1s = (float*)sym(g_ph1s);
    float* fpt = (float*)sym(g_fpt);   float* fps = (float*)sym(g_fps);
    __half* fpth = (__half*)sym(g_fpth); __half* fpsh = (__half*)sym(g_fpsh);
    float* dinv = (float*)sym(g_dinv); float* dinvp = (float*)sym(g_dinvp);
    unsigned* Ab = (unsigned*)sym(g_Abits);
    unsigned* Pb = (unsigned*)sym(g_Pbits);
    __half* Mfh = (__half*)sym(g_Mfh); __half* Pfh = (__half*)sym(g_Pfh);
    float* pp = (float*)sym(g_pp);
    float* rowp1 = (float*)sym(g_rowp1); float* colp1 = (float*)sym(g_colp1);
    float* rowp2 = (float*)sym(g_rowp2); float* colp2 = (float*)sym(g_colp2);
    float* pos1 = (float*)sym(g_pos1);   float* pos2 = (float*)sym(g_pos2);

    embed_kernel<<<dim3(Nn/16, 2), 128>>>(fs, ft, We, be);
    gramA_kernel<<<528, 256>>>();
    dinv_kernel<<<8, 256>>>();
    build_mfh<<<(Nn*(Nn/8) + 255)/256, 256>>>(Ab, dinv, Mfh, Nn, 64);
    prop_mma3<<<dim3(16, 16), 256>>>(Mfh, feth, fesh, pp, Nn, 8);
    prop_combine3<<<dim3(256, 2), 256>>>(h1t, h1s, h1th, h1sh, Nn, 8);
    prop_mma3<<<dim3(16, 16), 256>>>(Mfh, h1th, h1sh, pp, Nn, 8);
    prop_combine3<<<dim3(256, 2), 256>>>(h2t, h2s, nullptr, nullptr, Nn, 8);
    lin_kernel<<<dim3(Nn/16, 2), 128>>>(fet, h1t, h2t, fes, h1s, h2s, 3, Wg, bg,
                                        fgt, fgs, fgth, fgsh, Wp, bp, 1);
    gramnce_h<<<dim3(32, 32), 256>>>(fgth, fgsh, rowp1, colp1, pos1, Nn);
    rank_kernel<<<Nn, 256>>>();
    gather_kernel<<<Kp, 128>>>();
    subbits_kernel<<<dim3(16, 16), 256>>>();
    dinvp_kernel<<<4, 256>>>();
    build_mfh<<<(Kp*(Kp/8) + 255)/256, 256>>>(Pb, dinvp, Pfh, Kp, 32);
    prop_mma3<<<dim3(8, 8), 256>>>(Pfh, nhth, nhsh, pp, Kp, 4);
    prop_combine3<<<dim3(128, 2), 256>>>(ph1t, ph1s, nullptr, nullptr, Kp, 4);
    lin_kernel<<<dim3(Kp/16, 2), 128>>>(nht, ph1t, nullptr, nhs, ph1s, nullptr, 2, Wgp, bgp,
                                        fpt, fps, fpth, fpsh, nullptr, nullptr, 0);
    gramnce_h<<<dim3(16, 16), 256>>>(fpth, fpsh, rowp2, colp2, pos2, Kp);
    final_kernel<<<1, 1024>>>(out);
}